// round 4
// baseline (speedup 1.0000x reference)
#include <cuda_runtime.h>
#include <math.h>

#define T_TOK 4096
#define DIM   1024
#define HID   512
#define NE    8
#define NSH   2
#define NSLOT (2 * T_TOK)   // 8192 routed slots total (top-2)

// ---------------- scratch (device globals; ~80 MB total) -------------------
// pointer role table: 0=x 1=router_w 2=router_b 3=w1 4=w3 5=w2 6=sw1 7=sw3 8=sw2
__device__ const float* g_ptr[9];

__device__ __align__(16) float g_gates[T_TOK * 2];
__device__ __align__(16) int   g_eidx[T_TOK * 2];
__device__ __align__(16) int   g_pos[T_TOK * 2];     // global slot index per (token, k)
__device__ __align__(16) int   g_counts[NE];
__device__ __align__(16) int   g_base[NE];           // exclusive prefix of counts
__device__ __align__(16) int   g_tok[NSLOT];
__device__ __align__(16) float g_slotgate[NSLOT];
__device__ __align__(16) float g_h[(size_t)NSLOT * HID];        // 16 MB
__device__ __align__(16) float g_y[(size_t)NSLOT * DIM];        // 32 MB
__device__ __align__(16) float g_hsh[(size_t)NSH * T_TOK * HID];// 16 MB
__device__ __align__(16) float g_ysh[(size_t)T_TOK * DIM];      // 16 MB

// ---------------- input-role detection (content + size based) --------------
__global__ void detect_kernel(const float* p0, const float* p1, const float* p2,
                              const float* p3, const float* p4, const float* p5,
                              const float* p6, const float* p7, const float* p8,
                              long long s0, long long s1, long long s2,
                              long long s3, long long s4, long long s5,
                              long long s6, long long s7, long long s8) {
    if (threadIdx.x != 0 || blockIdx.x != 0) return;
    const float* p[9] = {p0, p1, p2, p3, p4, p5, p6, p7, p8};
    long long sz[9] = {s0, s1, s2, s3, s4, s5, s6, s7, s8};

    // unit normalization: router_b is 8 elements (32 bytes)
    long long mn = sz[0];
    for (int i = 1; i < 9; i++) if (sz[i] < mn) mn = sz[i];
    long long unit = (mn == 32) ? 4 : 1;
    for (int i = 0; i < 9; i++) sz[i] /= unit;

    int pos_rb = -1, pos_rw = -1;
    int big[4]; int nb = 0;     // 4M-element buffers (x + 3 routed)
    int med[3]; int nm = 0;     // 1M-element buffers (3 shared)
    for (int i = 0; i < 9; i++) {
        if (sz[i] == 8) pos_rb = i;
        else if (sz[i] == 8192) pos_rw = i;
        else if (sz[i] == 4194304) { if (nb < 4) big[nb] = i; nb++; }
        else if (sz[i] == 1048576) { if (nm < 3) med[nm] = i; nm++; }
    }

    bool ok = (pos_rb >= 0 && pos_rw >= 0 && nb == 4 && nm == 3);
    int pos_x = -1;
    if (ok) {
        // x ~ N(0,1): mean|v| ~ 0.8; weights scaled 0.02: mean|v| ~ 0.016
        for (int j = 0; j < 4 && pos_x < 0; j++) {
            float s = 0.f;
            const float* q = p[big[j]];
            for (int k = 0; k < 1024; k++) s += fabsf(q[k]);
            if (s * (1.f / 1024.f) > 0.1f) pos_x = big[j];
        }
        if (pos_x < 0) ok = false;
    }

    if (!ok) {
        // fallback: dict order x, rw, rb, w1, w3, w2, sw1, sw3, sw2
        g_ptr[0] = p[0]; g_ptr[1] = p[1]; g_ptr[2] = p[2];
        g_ptr[3] = p[3]; g_ptr[4] = p[4]; g_ptr[5] = p[5];
        g_ptr[6] = p[6]; g_ptr[7] = p[7]; g_ptr[8] = p[8];
        return;
    }

    int tr[3]; int nt = 0;
    for (int j = 0; j < 4; j++) if (big[j] != pos_x) tr[nt++] = big[j];

    g_ptr[0] = p[pos_x];
    g_ptr[1] = p[pos_rw];
    g_ptr[2] = p[pos_rb];
    if (pos_x == 0) {
        // dict-style: trios appear as (w1, w3, w2) / (sw1, sw3, sw2)
        g_ptr[3] = p[tr[0]]; g_ptr[4] = p[tr[1]]; g_ptr[5] = p[tr[2]];
        g_ptr[6] = p[med[0]]; g_ptr[7] = p[med[1]]; g_ptr[8] = p[med[2]];
    } else {
        // alpha-style: trios appear as (w1, w2, w3) / (sw1, sw2, sw3)
        g_ptr[3] = p[tr[0]]; g_ptr[4] = p[tr[2]]; g_ptr[5] = p[tr[1]];
        g_ptr[6] = p[med[0]]; g_ptr[7] = p[med[2]]; g_ptr[8] = p[med[1]];
    }
}

// ---------------- router: logits, top-2, softmax gates ---------------------
__global__ void router_kernel() {
    const float* x  = g_ptr[0];
    const float* rw = g_ptr[1];
    const float* rb = g_ptr[2];
    int t = blockIdx.x * blockDim.y + threadIdx.y;
    if (t >= T_TOK) return;
    int lane = threadIdx.x;
    const float* xr = x + (size_t)t * DIM;

    float acc[NE];
#pragma unroll
    for (int e = 0; e < NE; e++) acc[e] = 0.f;
    for (int i = lane; i < DIM; i += 32) {
        float xv = xr[i];
        const float* w = rw + (size_t)i * NE;
#pragma unroll
        for (int e = 0; e < NE; e++) acc[e] += xv * w[e];
    }
#pragma unroll
    for (int e = 0; e < NE; e++) {
#pragma unroll
        for (int off = 16; off > 0; off >>= 1)
            acc[e] += __shfl_xor_sync(0xffffffffu, acc[e], off);
    }
    if (lane == 0) {
        float v[NE];
#pragma unroll
        for (int e = 0; e < NE; e++) v[e] = acc[e] + rb[e];
        int i0 = 0;
        for (int e = 1; e < NE; e++) if (v[e] > v[i0]) i0 = e;
        int i1 = (i0 == 0) ? 1 : 0;
        for (int e = 0; e < NE; e++) if (e != i0 && v[e] > v[i1]) i1 = e;
        float e1 = expf(v[i1] - v[i0]);
        float g0 = 1.f / (1.f + e1);
        float g1 = e1 * g0;
        g_gates[t * 2 + 0] = g0;
        g_gates[t * 2 + 1] = g1;
        g_eidx[t * 2 + 0] = i0;
        g_eidx[t * 2 + 1] = i1;
    }
}

// ---------------- deterministic gather with global slot packing ------------
__global__ void gather_kernel() {
    __shared__ int s_cnt[NE];
    __shared__ int s_base[NE];
    int wid = threadIdx.x / 32;
    int lane = threadIdx.x % 32;

    // pass 1: per-expert counts
    if (wid < NE) {
        int e = wid, cnt = 0;
        for (int chunk = 0; chunk < T_TOK; chunk += 32) {
            int t = chunk + lane;
            bool hit = (g_eidx[t * 2] == e) || (g_eidx[t * 2 + 1] == e);
            cnt += __popc(__ballot_sync(0xffffffffu, hit));
        }
        if (lane == 0) s_cnt[e] = cnt;
    }
    __syncthreads();
    if (threadIdx.x == 0) {
        int acc = 0;
        for (int e = 0; e < NE; e++) { s_base[e] = acc; acc += s_cnt[e]; }
    }
    __syncthreads();

    // pass 2: fill
    if (wid < NE) {
        int e = wid;
        int base = s_base[e];
        int run = 0;
        for (int chunk = 0; chunk < T_TOK; chunk += 32) {
            int t = chunk + lane;
            int k = -1;
            if (g_eidx[t * 2] == e) k = 0;
            else if (g_eidx[t * 2 + 1] == e) k = 1;
            unsigned mask = __ballot_sync(0xffffffffu, k >= 0);
            if (k >= 0) {
                int slot = base + run + __popc(mask & ((1u << lane) - 1u));
                g_tok[slot] = t;
                g_pos[t * 2 + k] = slot;
                g_slotgate[slot] = g_gates[t * 2 + k];
            }
            run += __popc(mask);
        }
        if (lane == 0) { g_counts[e] = run; g_base[e] = base; }
    }
}

// ---------------- GEMM1: h = silu(x@w1) * (x@w3) ---------------------------
// block tile 128 rows x 64 cols, 256 threads, 8x4 microtile, K panel 16
template <bool ROUTED>
__global__ void __launch_bounds__(256) gemm1_kernel() {
    const float* x = g_ptr[0];
    int e = blockIdx.z;
    int cnt  = ROUTED ? g_counts[e] : T_TOK;
    int base = ROUTED ? g_base[e] : 0;
    int row0 = blockIdx.y * 128;
    if (row0 >= cnt) return;
    int h0 = blockIdx.x * 64;

    const float* w1 = (ROUTED ? g_ptr[3] : g_ptr[6]) + (size_t)e * DIM * HID;
    const float* w3 = (ROUTED ? g_ptr[4] : g_ptr[7]) + (size_t)e * DIM * HID;
    float* hout = ROUTED ? (g_h + (size_t)base * HID)
                         : (g_hsh + (size_t)e * T_TOK * HID);
    const int* toklist = ROUTED ? (g_tok + base) : nullptr;

    __shared__ float As[16][132];
    __shared__ float Bs1[16][64];
    __shared__ float Bs3[16][64];

    int tid = threadIdx.x;
    int tx = tid & 15;
    int ty = tid >> 4;

    int arow = tid >> 2;            // 0..63
    int akq  = (tid & 3) * 4;       // 0,4,8,12
    int r_a0 = row0 + arow;
    int r_a1 = row0 + arow + 64;
    const float* xrow0 = nullptr;
    const float* xrow1 = nullptr;
    if (r_a0 < cnt) { int tk = ROUTED ? toklist[r_a0] : r_a0; xrow0 = x + (size_t)tk * DIM; }
    if (r_a1 < cnt) { int tk = ROUTED ? toklist[r_a1] : r_a1; xrow1 = x + (size_t)tk * DIM; }

    int bk = tid >> 4;              // 0..15
    int bh = (tid & 15) * 4;        // 0..60

    float acc1[8][4], acc3[8][4];
#pragma unroll
    for (int i = 0; i < 8; i++)
#pragma unroll
        for (int j = 0; j < 4; j++) { acc1[i][j] = 0.f; acc3[i][j] = 0.f; }

    for (int k0 = 0; k0 < DIM; k0 += 16) {
        float4 a0 = xrow0 ? *(const float4*)(xrow0 + k0 + akq) : make_float4(0.f, 0.f, 0.f, 0.f);
        float4 a1 = xrow1 ? *(const float4*)(xrow1 + k0 + akq) : make_float4(0.f, 0.f, 0.f, 0.f);
        float4 b1v = *(const float4*)(w1 + (size_t)(k0 + bk) * HID + h0 + bh);
        float4 b3v = *(const float4*)(w3 + (size_t)(k0 + bk) * HID + h0 + bh);
        __syncthreads();
        As[akq + 0][arow] = a0.x; As[akq + 1][arow] = a0.y;
        As[akq + 2][arow] = a0.z; As[akq + 3][arow] = a0.w;
        As[akq + 0][arow + 64] = a1.x; As[akq + 1][arow + 64] = a1.y;
        As[akq + 2][arow + 64] = a1.z; As[akq + 3][arow + 64] = a1.w;
        *(float4*)&Bs1[bk][bh] = b1v;
        *(float4*)&Bs3[bk][bh] = b3v;
        __syncthreads();
#pragma unroll
        for (int kk = 0; kk < 16; kk++) {
            float a[8];
#pragma unroll
            for (int i = 0; i < 8; i++) a[i] = As[kk][ty + 16 * i];
            float4 b1r = *(const float4*)&Bs1[kk][tx * 4];
            float4 b3r = *(const float4*)&Bs3[kk][tx * 4];
            float b1a[4] = {b1r.x, b1r.y, b1r.z, b1r.w};
            float b3a[4] = {b3r.x, b3r.y, b3r.z, b3r.w};
#pragma unroll
            for (int i = 0; i < 8; i++)
#pragma unroll
                for (int j = 0; j < 4; j++) {
                    acc1[i][j] += a[i] * b1a[j];
                    acc3[i][j] += a[i] * b3a[j];
                }
        }
    }

#pragma unroll
    for (int i = 0; i < 8; i++) {
        int r = row0 + ty + 16 * i;
        if (r < cnt) {
            float4 o;
            float v;
            v = acc1[i][0]; o.x = (v / (1.f + expf(-v))) * acc3[i][0];
            v = acc1[i][1]; o.y = (v / (1.f + expf(-v))) * acc3[i][1];
            v = acc1[i][2]; o.z = (v / (1.f + expf(-v))) * acc3[i][2];
            v = acc1[i][3]; o.w = (v / (1.f + expf(-v))) * acc3[i][3];
            *(float4*)(hout + (size_t)r * HID + h0 + tx * 4) = o;
        }
    }
}

// ---------------- GEMM2: y = (h @ w2) * gate (routed) / sum shared ---------
template <bool ROUTED>
__global__ void __launch_bounds__(256) gemm2_kernel() {
    int e = blockIdx.z;
    int cnt  = ROUTED ? g_counts[e] : T_TOK;
    int base = ROUTED ? g_base[e] : 0;
    int row0 = blockIdx.y * 128;
    if (row0 >= cnt) return;
    int d0 = blockIdx.x * 64;

    float* y = ROUTED ? (g_y + (size_t)base * DIM) : g_ysh;

    __shared__ float As[16][132];
    __shared__ float Bs[16][64];

    int tid = threadIdx.x;
    int tx = tid & 15;
    int ty = tid >> 4;

    int arow = tid >> 2;
    int akq  = (tid & 3) * 4;
    int r_a0 = row0 + arow;
    int r_a1 = row0 + arow + 64;

    int bk = tid >> 4;
    int bh = (tid & 15) * 4;

    float acc[8][4];
#pragma unroll
    for (int i = 0; i < 8; i++)
#pragma unroll
        for (int j = 0; j < 4; j++) acc[i][j] = 0.f;

    int nloop = ROUTED ? 1 : NSH;
    for (int s = 0; s < nloop; s++) {
        const float* A  = ROUTED ? (g_h + (size_t)base * HID)
                                 : (g_hsh + (size_t)s * T_TOK * HID);
        const float* w2 = (ROUTED ? g_ptr[5] : g_ptr[8])
                        + (size_t)(ROUTED ? e : s) * HID * DIM;
        const float* ar0 = (r_a0 < cnt) ? (A + (size_t)r_a0 * HID) : nullptr;
        const float* ar1 = (r_a1 < cnt) ? (A + (size_t)r_a1 * HID) : nullptr;

        for (int k0 = 0; k0 < HID; k0 += 16) {
            float4 a0 = ar0 ? *(const float4*)(ar0 + k0 + akq) : make_float4(0.f, 0.f, 0.f, 0.f);
            float4 a1 = ar1 ? *(const float4*)(ar1 + k0 + akq) : make_float4(0.f, 0.f, 0.f, 0.f);
            float4 bv = *(const float4*)(w2 + (size_t)(k0 + bk) * DIM + d0 + bh);
            __syncthreads();
            As[akq + 0][arow] = a0.x; As[akq + 1][arow] = a0.y;
            As[akq + 2][arow] = a0.z; As[akq + 3][arow] = a0.w;
            As[akq + 0][arow + 64] = a1.x; As[akq + 1][arow + 64] = a1.y;
            As[akq + 2][arow + 64] = a1.z; As[akq + 3][arow + 64] = a1.w;
            *(float4*)&Bs[bk][bh] = bv;
            __syncthreads();
#pragma unroll
            for (int kk = 0; kk < 16; kk++) {
                float a[8];
#pragma unroll
                for (int i = 0; i < 8; i++) a[i] = As[kk][ty + 16 * i];
                float4 br = *(const float4*)&Bs[kk][tx * 4];
                float ba[4] = {br.x, br.y, br.z, br.w};
#pragma unroll
                for (int i = 0; i < 8; i++)
#pragma unroll
                    for (int j = 0; j < 4; j++) acc[i][j] += a[i] * ba[j];
            }
        }
    }

#pragma unroll
    for (int i = 0; i < 8; i++) {
        int r = row0 + ty + 16 * i;
        if (r < cnt) {
            float scale = ROUTED ? g_slotgate[base + r] : 1.f;
            float4 o;
            o.x = acc[i][0] * scale; o.y = acc[i][1] * scale;
            o.z = acc[i][2] * scale; o.w = acc[i][3] * scale;
            *(float4*)(y + (size_t)r * DIM + d0 + tx * 4) = o;
        }
    }
}

// ---------------- combine: out = shared + y[slot0] + y[slot1] --------------
__global__ void combine_kernel(float* __restrict__ out) {
    int idx = blockIdx.x * blockDim.x + threadIdx.x;   // over T*DIM/4
    int t  = idx / (DIM / 4);
    int d4 = idx % (DIM / 4);
    int p0 = g_pos[t * 2 + 0];
    int p1 = g_pos[t * 2 + 1];
    float4 a = ((const float4*)(g_ysh + (size_t)t * DIM))[d4];
    float4 b = ((const float4*)(g_y + (size_t)p0 * DIM))[d4];
    float4 c = ((const float4*)(g_y + (size_t)p1 * DIM))[d4];
    float4 o;
    o.x = a.x + b.x + c.x;
    o.y = a.y + b.y + c.y;
    o.z = a.z + b.z + c.z;
    o.w = a.w + b.w + c.w;
    ((float4*)out)[idx] = o;
}

// ---------------- launcher --------------------------------------------------
extern "C" void kernel_launch(void* const* d_in, const int* in_sizes, int n_in,
                              void* d_out, int out_size) {
    detect_kernel<<<1, 32>>>(
        (const float*)d_in[0], (const float*)d_in[1], (const float*)d_in[2],
        (const float*)d_in[3], (const float*)d_in[4], (const float*)d_in[5],
        (const float*)d_in[6], (const float*)d_in[7], (const float*)d_in[8],
        (long long)in_sizes[0], (long long)in_sizes[1], (long long)in_sizes[2],
        (long long)in_sizes[3], (long long)in_sizes[4], (long long)in_sizes[5],
        (long long)in_sizes[6], (long long)in_sizes[7], (long long)in_sizes[8]);

    router_kernel<<<T_TOK / 4, dim3(32, 4)>>>();
    gather_kernel<<<1, NE * 32>>>();

    // routed experts on gathered rows
    gemm1_kernel<true><<<dim3(HID / 64, T_TOK / 128, NE), 256>>>();
    gemm2_kernel<true><<<dim3(DIM / 64, T_TOK / 128, NE), 256>>>();

    // shared experts (dense over all tokens)
    gemm1_kernel<false><<<dim3(HID / 64, T_TOK / 128, NSH), 256>>>();
    gemm2_kernel<false><<<dim3(DIM / 64, T_TOK / 128, 1), 256>>>();

    combine_kernel<<<(T_TOK * DIM / 4) / 256, 256>>>((float*)d_out);
}

// round 5
// speedup vs baseline: 1.3864x; 1.3864x over previous
#include <cuda_runtime.h>
#include <math.h>
#include <stdint.h>

#define T_TOK 4096
#define DIM   1024
#define HID   512
#define NE    8
#define NSH   2
#define NSLOT (2 * T_TOK)   // 8192 routed slots total (top-2)

// ---------------- scratch (device globals; no runtime allocation) ----------
// pointer role table: 0=x 1=router_w 2=router_b 3=w1 4=w3 5=w2 6=sw1 7=sw3 8=sw2
__device__ const float* g_ptr[9];

__device__ __align__(16) float g_gates[T_TOK * 2];
__device__ __align__(16) int   g_eidx[T_TOK * 2];
__device__ __align__(16) int   g_pos[T_TOK * 2];
__device__ __align__(16) int   g_counts[NE];
__device__ __align__(16) int   g_base[NE];
__device__ __align__(16) int   g_tok[NSLOT];
__device__ __align__(16) float g_slotgate[NSLOT];
__device__ __align__(16) float g_h[(size_t)NSLOT * HID];        // 16 MB
__device__ __align__(16) float g_y[(size_t)NSLOT * DIM];        // 32 MB
__device__ __align__(16) float g_hsh[(size_t)NSH * T_TOK * HID];// 16 MB
__device__ __align__(16) float g_ysh[(size_t)T_TOK * DIM];      // 16 MB

// ---------------- tf32 helpers ---------------------------------------------
__device__ __forceinline__ uint32_t f2tf32(float f) {
    uint32_t u;
    asm("cvt.rna.tf32.f32 %0, %1;" : "=r"(u) : "f"(f));
    return u;
}

__device__ __forceinline__ void mma_tf32(float c[4],
                                         uint32_t a0, uint32_t a1, uint32_t a2, uint32_t a3,
                                         uint32_t b0, uint32_t b1) {
    asm volatile(
        "mma.sync.aligned.m16n8k8.row.col.f32.tf32.tf32.f32 "
        "{%0,%1,%2,%3},{%4,%5,%6,%7},{%8,%9},{%0,%1,%2,%3};"
        : "+f"(c[0]), "+f"(c[1]), "+f"(c[2]), "+f"(c[3])
        : "r"(a0), "r"(a1), "r"(a2), "r"(a3), "r"(b0), "r"(b1));
}

// ---------------- input-role detection (content + size based) --------------
__global__ void detect_kernel(const float* p0, const float* p1, const float* p2,
                              const float* p3, const float* p4, const float* p5,
                              const float* p6, const float* p7, const float* p8,
                              long long s0, long long s1, long long s2,
                              long long s3, long long s4, long long s5,
                              long long s6, long long s7, long long s8) {
    if (threadIdx.x != 0 || blockIdx.x != 0) return;
    const float* p[9] = {p0, p1, p2, p3, p4, p5, p6, p7, p8};
    long long sz[9] = {s0, s1, s2, s3, s4, s5, s6, s7, s8};

    long long mn = sz[0];
    for (int i = 1; i < 9; i++) if (sz[i] < mn) mn = sz[i];
    long long unit = (mn == 32) ? 4 : 1;
    for (int i = 0; i < 9; i++) sz[i] /= unit;

    int pos_rb = -1, pos_rw = -1;
    int big[4]; int nb = 0;
    int med[3]; int nm = 0;
    for (int i = 0; i < 9; i++) {
        if (sz[i] == 8) pos_rb = i;
        else if (sz[i] == 8192) pos_rw = i;
        else if (sz[i] == 4194304) { if (nb < 4) big[nb] = i; nb++; }
        else if (sz[i] == 1048576) { if (nm < 3) med[nm] = i; nm++; }
    }

    bool ok = (pos_rb >= 0 && pos_rw >= 0 && nb == 4 && nm == 3);
    int pos_x = -1;
    if (ok) {
        for (int j = 0; j < 4 && pos_x < 0; j++) {
            float s = 0.f;
            const float* q = p[big[j]];
            for (int k = 0; k < 1024; k++) s += fabsf(q[k]);
            if (s * (1.f / 1024.f) > 0.1f) pos_x = big[j];
        }
        if (pos_x < 0) ok = false;
    }

    if (!ok) {
        g_ptr[0] = p[0]; g_ptr[1] = p[1]; g_ptr[2] = p[2];
        g_ptr[3] = p[3]; g_ptr[4] = p[4]; g_ptr[5] = p[5];
        g_ptr[6] = p[6]; g_ptr[7] = p[7]; g_ptr[8] = p[8];
        return;
    }

    int tr[3]; int nt = 0;
    for (int j = 0; j < 4; j++) if (big[j] != pos_x) tr[nt++] = big[j];

    g_ptr[0] = p[pos_x];
    g_ptr[1] = p[pos_rw];
    g_ptr[2] = p[pos_rb];
    if (pos_x == 0) {
        // dict-style: trios appear as (w1, w3, w2)
        g_ptr[3] = p[tr[0]]; g_ptr[4] = p[tr[1]]; g_ptr[5] = p[tr[2]];
        g_ptr[6] = p[med[0]]; g_ptr[7] = p[med[1]]; g_ptr[8] = p[med[2]];
    } else {
        // alpha-style: trios appear as (w1, w2, w3)
        g_ptr[3] = p[tr[0]]; g_ptr[4] = p[tr[2]]; g_ptr[5] = p[tr[1]];
        g_ptr[6] = p[med[0]]; g_ptr[7] = p[med[2]]; g_ptr[8] = p[med[1]];
    }
}

// ---------------- router: logits, top-2, softmax gates (pure fp32) ---------
__global__ void router_kernel() {
    const float* x  = g_ptr[0];
    const float* rw = g_ptr[1];
    const float* rb = g_ptr[2];
    int t = blockIdx.x * blockDim.y + threadIdx.y;
    if (t >= T_TOK) return;
    int lane = threadIdx.x;
    const float* xr = x + (size_t)t * DIM;

    float acc[NE];
#pragma unroll
    for (int e = 0; e < NE; e++) acc[e] = 0.f;
    for (int i = lane; i < DIM; i += 32) {
        float xv = xr[i];
        const float* w = rw + (size_t)i * NE;
#pragma unroll
        for (int e = 0; e < NE; e++) acc[e] += xv * w[e];
    }
#pragma unroll
    for (int e = 0; e < NE; e++) {
#pragma unroll
        for (int off = 16; off > 0; off >>= 1)
            acc[e] += __shfl_xor_sync(0xffffffffu, acc[e], off);
    }
    if (lane == 0) {
        float v[NE];
#pragma unroll
        for (int e = 0; e < NE; e++) v[e] = acc[e] + rb[e];
        int i0 = 0;
        for (int e = 1; e < NE; e++) if (v[e] > v[i0]) i0 = e;
        int i1 = (i0 == 0) ? 1 : 0;
        for (int e = 0; e < NE; e++) if (e != i0 && v[e] > v[i1]) i1 = e;
        float e1 = expf(v[i1] - v[i0]);
        float g0 = 1.f / (1.f + e1);
        float g1 = e1 * g0;
        g_gates[t * 2 + 0] = g0;
        g_gates[t * 2 + 1] = g1;
        g_eidx[t * 2 + 0] = i0;
        g_eidx[t * 2 + 1] = i1;
    }
}

// ---------------- deterministic gather with global slot packing ------------
__global__ void gather_kernel() {
    __shared__ int s_cnt[NE];
    __shared__ int s_base[NE];
    int wid = threadIdx.x / 32;
    int lane = threadIdx.x % 32;

    if (wid < NE) {
        int e = wid, cnt = 0;
        for (int chunk = 0; chunk < T_TOK; chunk += 32) {
            int t = chunk + lane;
            bool hit = (g_eidx[t * 2] == e) || (g_eidx[t * 2 + 1] == e);
            cnt += __popc(__ballot_sync(0xffffffffu, hit));
        }
        if (lane == 0) s_cnt[e] = cnt;
    }
    __syncthreads();
    if (threadIdx.x == 0) {
        int acc = 0;
        for (int e = 0; e < NE; e++) { s_base[e] = acc; acc += s_cnt[e]; }
    }
    __syncthreads();

    if (wid < NE) {
        int e = wid;
        int base = s_base[e];
        int run = 0;
        for (int chunk = 0; chunk < T_TOK; chunk += 32) {
            int t = chunk + lane;
            int k = -1;
            if (g_eidx[t * 2] == e) k = 0;
            else if (g_eidx[t * 2 + 1] == e) k = 1;
            unsigned mask = __ballot_sync(0xffffffffu, k >= 0);
            if (k >= 0) {
                int slot = base + run + __popc(mask & ((1u << lane) - 1u));
                g_tok[slot] = t;
                g_pos[t * 2 + k] = slot;
                g_slotgate[slot] = g_gates[t * 2 + k];
            }
            run += __popc(mask);
        }
        if (lane == 0) { g_counts[e] = run; g_base[e] = base; }
    }
}

// ---------------- GEMM1 (tf32 tensor cores): h = silu(x@w1)*(x@w3) ---------
// block tile 128x64, BK=32, 8 warps (4x2), warp tile 32x32, m16n8k8 frags
template <bool ROUTED>
__global__ void __launch_bounds__(256) gemm1_kernel() {
    const float* x = g_ptr[0];
    int e = blockIdx.z;
    int cnt  = ROUTED ? g_counts[e] : T_TOK;
    int base = ROUTED ? g_base[e] : 0;
    int row0 = blockIdx.y * 128;
    if (row0 >= cnt) return;
    int h0 = blockIdx.x * 64;

    const float* w1 = (ROUTED ? g_ptr[3] : g_ptr[6]) + (size_t)e * DIM * HID;
    const float* w3 = (ROUTED ? g_ptr[4] : g_ptr[7]) + (size_t)e * DIM * HID;
    float* hout = ROUTED ? (g_h + (size_t)base * HID)
                         : (g_hsh + (size_t)e * T_TOK * HID);
    const int* toklist = ROUTED ? (g_tok + base) : nullptr;

    __shared__ uint32_t As[32][136];   // [k][m], stride%32==8 -> conflict-free frag reads
    __shared__ uint32_t Bs1[32][72];   // [k][n], stride%32==8
    __shared__ uint32_t Bs3[32][72];

    int tid = threadIdx.x;
    // A loader: 2 threads per row, each covers 16 k
    int lrow = tid >> 1;
    int lkq  = (tid & 1) * 16;
    int r_l = row0 + lrow;
    const float* xrow = nullptr;
    if (r_l < cnt) { int tk = ROUTED ? toklist[r_l] : r_l; xrow = x + (size_t)tk * DIM; }
    // B loader: 8 threads per k-row, each covers 8 n
    int lbk = tid >> 3;
    int lbn = (tid & 7) * 8;

    int wid = tid >> 5, lane = tid & 31;
    int wm = (wid >> 1) * 32;
    int wn = (wid & 1) * 32;
    int g = lane >> 2, tg = lane & 3;

    float acc1[2][4][4], acc3[2][4][4];
#pragma unroll
    for (int i = 0; i < 2; i++)
#pragma unroll
        for (int j = 0; j < 4; j++)
#pragma unroll
            for (int c = 0; c < 4; c++) { acc1[i][j][c] = 0.f; acc3[i][j][c] = 0.f; }

    for (int k0 = 0; k0 < DIM; k0 += 32) {
        float4 av[4];
#pragma unroll
        for (int j = 0; j < 4; j++)
            av[j] = xrow ? *(const float4*)(xrow + k0 + lkq + 4 * j)
                         : make_float4(0.f, 0.f, 0.f, 0.f);
        float4 b1v[2], b3v[2];
#pragma unroll
        for (int j = 0; j < 2; j++) {
            b1v[j] = *(const float4*)(w1 + (size_t)(k0 + lbk) * HID + h0 + lbn + 4 * j);
            b3v[j] = *(const float4*)(w3 + (size_t)(k0 + lbk) * HID + h0 + lbn + 4 * j);
        }
        __syncthreads();
#pragma unroll
        for (int j = 0; j < 4; j++) {
            As[lkq + 4 * j + 0][lrow] = f2tf32(av[j].x);
            As[lkq + 4 * j + 1][lrow] = f2tf32(av[j].y);
            As[lkq + 4 * j + 2][lrow] = f2tf32(av[j].z);
            As[lkq + 4 * j + 3][lrow] = f2tf32(av[j].w);
        }
#pragma unroll
        for (int j = 0; j < 2; j++) {
            uint4 u1, u3;
            u1.x = f2tf32(b1v[j].x); u1.y = f2tf32(b1v[j].y);
            u1.z = f2tf32(b1v[j].z); u1.w = f2tf32(b1v[j].w);
            u3.x = f2tf32(b3v[j].x); u3.y = f2tf32(b3v[j].y);
            u3.z = f2tf32(b3v[j].z); u3.w = f2tf32(b3v[j].w);
            *(uint4*)&Bs1[lbk][lbn + 4 * j] = u1;
            *(uint4*)&Bs3[lbk][lbn + 4 * j] = u3;
        }
        __syncthreads();

#pragma unroll
        for (int kk = 0; kk < 32; kk += 8) {
            uint32_t a[2][4];
#pragma unroll
            for (int i = 0; i < 2; i++) {
                int m = wm + i * 16 + g;
                a[i][0] = As[kk + tg][m];
                a[i][1] = As[kk + tg][m + 8];
                a[i][2] = As[kk + tg + 4][m];
                a[i][3] = As[kk + tg + 4][m + 8];
            }
#pragma unroll
            for (int j = 0; j < 4; j++) {
                int n = wn + j * 8 + g;
                uint32_t p0 = Bs1[kk + tg][n];
                uint32_t p1 = Bs1[kk + tg + 4][n];
                uint32_t q0 = Bs3[kk + tg][n];
                uint32_t q1 = Bs3[kk + tg + 4][n];
#pragma unroll
                for (int i = 0; i < 2; i++) {
                    mma_tf32(acc1[i][j], a[i][0], a[i][1], a[i][2], a[i][3], p0, p1);
                    mma_tf32(acc3[i][j], a[i][0], a[i][1], a[i][2], a[i][3], q0, q1);
                }
            }
        }
    }

#pragma unroll
    for (int i = 0; i < 2; i++) {
        int r0 = row0 + wm + i * 16 + g;
        int r1 = r0 + 8;
#pragma unroll
        for (int j = 0; j < 4; j++) {
            int c = h0 + wn + j * 8 + 2 * tg;
            if (r0 < cnt) {
                float v0 = acc1[i][j][0], v1 = acc1[i][j][1];
                float2 o;
                o.x = (v0 / (1.f + expf(-v0))) * acc3[i][j][0];
                o.y = (v1 / (1.f + expf(-v1))) * acc3[i][j][1];
                *(float2*)(hout + (size_t)r0 * HID + c) = o;
            }
            if (r1 < cnt) {
                float v2 = acc1[i][j][2], v3 = acc1[i][j][3];
                float2 o;
                o.x = (v2 / (1.f + expf(-v2))) * acc3[i][j][2];
                o.y = (v3 / (1.f + expf(-v3))) * acc3[i][j][3];
                *(float2*)(hout + (size_t)r1 * HID + c) = o;
            }
        }
    }
}

// ---------------- GEMM2 (tf32): y = (h @ w2) * gate / shared sum -----------
template <bool ROUTED>
__global__ void __launch_bounds__(256) gemm2_kernel() {
    int e = blockIdx.z;
    int cnt  = ROUTED ? g_counts[e] : T_TOK;
    int base = ROUTED ? g_base[e] : 0;
    int row0 = blockIdx.y * 128;
    if (row0 >= cnt) return;
    int d0 = blockIdx.x * 64;

    float* y = ROUTED ? (g_y + (size_t)base * DIM) : g_ysh;

    __shared__ uint32_t As[32][136];
    __shared__ uint32_t Bs[32][72];

    int tid = threadIdx.x;
    int lrow = tid >> 1;
    int lkq  = (tid & 1) * 16;
    int r_l = row0 + lrow;
    int lbk = tid >> 3;
    int lbn = (tid & 7) * 8;

    int wid = tid >> 5, lane = tid & 31;
    int wm = (wid >> 1) * 32;
    int wn = (wid & 1) * 32;
    int g = lane >> 2, tg = lane & 3;

    float acc[2][4][4];
#pragma unroll
    for (int i = 0; i < 2; i++)
#pragma unroll
        for (int j = 0; j < 4; j++)
#pragma unroll
            for (int c = 0; c < 4; c++) acc[i][j][c] = 0.f;

    int nloop = ROUTED ? 1 : NSH;
    for (int s = 0; s < nloop; s++) {
        const float* A  = ROUTED ? (g_h + (size_t)base * HID)
                                 : (g_hsh + (size_t)s * T_TOK * HID);
        const float* w2 = (ROUTED ? g_ptr[5] : g_ptr[8])
                        + (size_t)(ROUTED ? e : s) * HID * DIM;
        const float* arow = (r_l < cnt) ? (A + (size_t)r_l * HID) : nullptr;

        for (int k0 = 0; k0 < HID; k0 += 32) {
            float4 av[4];
#pragma unroll
            for (int j = 0; j < 4; j++)
                av[j] = arow ? *(const float4*)(arow + k0 + lkq + 4 * j)
                             : make_float4(0.f, 0.f, 0.f, 0.f);
            float4 bv[2];
#pragma unroll
            for (int j = 0; j < 2; j++)
                bv[j] = *(const float4*)(w2 + (size_t)(k0 + lbk) * DIM + d0 + lbn + 4 * j);
            __syncthreads();
#pragma unroll
            for (int j = 0; j < 4; j++) {
                As[lkq + 4 * j + 0][lrow] = f2tf32(av[j].x);
                As[lkq + 4 * j + 1][lrow] = f2tf32(av[j].y);
                As[lkq + 4 * j + 2][lrow] = f2tf32(av[j].z);
                As[lkq + 4 * j + 3][lrow] = f2tf32(av[j].w);
            }
#pragma unroll
            for (int j = 0; j < 2; j++) {
                uint4 u;
                u.x = f2tf32(bv[j].x); u.y = f2tf32(bv[j].y);
                u.z = f2tf32(bv[j].z); u.w = f2tf32(bv[j].w);
                *(uint4*)&Bs[lbk][lbn + 4 * j] = u;
            }
            __syncthreads();

#pragma unroll
            for (int kk = 0; kk < 32; kk += 8) {
                uint32_t a[2][4];
#pragma unroll
                for (int i = 0; i < 2; i++) {
                    int m = wm + i * 16 + g;
                    a[i][0] = As[kk + tg][m];
                    a[i][1] = As[kk + tg][m + 8];
                    a[i][2] = As[kk + tg + 4][m];
                    a[i][3] = As[kk + tg + 4][m + 8];
                }
#pragma unroll
                for (int j = 0; j < 4; j++) {
                    int n = wn + j * 8 + g;
                    uint32_t p0 = Bs[kk + tg][n];
                    uint32_t p1 = Bs[kk + tg + 4][n];
#pragma unroll
                    for (int i = 0; i < 2; i++)
                        mma_tf32(acc[i][j], a[i][0], a[i][1], a[i][2], a[i][3], p0, p1);
                }
            }
        }
    }

#pragma unroll
    for (int i = 0; i < 2; i++) {
        int r0 = row0 + wm + i * 16 + g;
        int r1 = r0 + 8;
        float sc0 = (ROUTED && r0 < cnt) ? g_slotgate[base + r0] : 1.f;
        float sc1 = (ROUTED && r1 < cnt) ? g_slotgate[base + r1] : 1.f;
#pragma unroll
        for (int j = 0; j < 4; j++) {
            int c = d0 + wn + j * 8 + 2 * tg;
            if (r0 < cnt) {
                float2 o;
                o.x = acc[i][j][0] * sc0;
                o.y = acc[i][j][1] * sc0;
                *(float2*)(y + (size_t)r0 * DIM + c) = o;
            }
            if (r1 < cnt) {
                float2 o;
                o.x = acc[i][j][2] * sc1;
                o.y = acc[i][j][3] * sc1;
                *(float2*)(y + (size_t)r1 * DIM + c) = o;
            }
        }
    }
}

// ---------------- combine: out = shared + y[slot0] + y[slot1] --------------
__global__ void combine_kernel(float* __restrict__ out) {
    int idx = blockIdx.x * blockDim.x + threadIdx.x;   // over T*DIM/4
    int t  = idx / (DIM / 4);
    int d4 = idx % (DIM / 4);
    int p0 = g_pos[t * 2 + 0];
    int p1 = g_pos[t * 2 + 1];
    float4 a = ((const float4*)(g_ysh + (size_t)t * DIM))[d4];
    float4 b = ((const float4*)(g_y + (size_t)p0 * DIM))[d4];
    float4 c = ((const float4*)(g_y + (size_t)p1 * DIM))[d4];
    float4 o;
    o.x = a.x + b.x + c.x;
    o.y = a.y + b.y + c.y;
    o.z = a.z + b.z + c.z;
    o.w = a.w + b.w + c.w;
    ((float4*)out)[idx] = o;
}

// ---------------- launcher --------------------------------------------------
extern "C" void kernel_launch(void* const* d_in, const int* in_sizes, int n_in,
                              void* d_out, int out_size) {
    detect_kernel<<<1, 32>>>(
        (const float*)d_in[0], (const float*)d_in[1], (const float*)d_in[2],
        (const float*)d_in[3], (const float*)d_in[4], (const float*)d_in[5],
        (const float*)d_in[6], (const float*)d_in[7], (const float*)d_in[8],
        (long long)in_sizes[0], (long long)in_sizes[1], (long long)in_sizes[2],
        (long long)in_sizes[3], (long long)in_sizes[4], (long long)in_sizes[5],
        (long long)in_sizes[6], (long long)in_sizes[7], (long long)in_sizes[8]);

    router_kernel<<<T_TOK / 4, dim3(32, 4)>>>();
    gather_kernel<<<1, NE * 32>>>();

    // routed experts on gathered rows
    gemm1_kernel<true><<<dim3(HID / 64, T_TOK / 128, NE), 256>>>();
    gemm2_kernel<true><<<dim3(DIM / 64, T_TOK / 128, NE), 256>>>();

    // shared experts (dense over all tokens)
    gemm1_kernel<false><<<dim3(HID / 64, T_TOK / 128, NSH), 256>>>();
    gemm2_kernel<false><<<dim3(DIM / 64, T_TOK / 128, 1), 256>>>();

    combine_kernel<<<(T_TOK * DIM / 4) / 256, 256>>>((float*)d_out);
}

// round 6
// speedup vs baseline: 2.1683x; 1.5640x over previous
#include <cuda_runtime.h>
#include <math.h>
#include <stdint.h>

#define T_TOK 4096
#define DIM   1024
#define HID   512
#define NE    8
#define NSH   2
#define NSLOT (2 * T_TOK)

// offsets (floats) inside g_wt pre-converted scratch
#define OFF_X   0
#define OFF_W1  4194304
#define OFF_W3  8388608
#define OFF_W2  12582912
#define OFF_SW1 16777216
#define OFF_SW3 17825792
#define OFF_SW2 18874368
#define WT_TOTAL 19922944   // floats (76 MB)

// ---------------- scratch (device globals; no runtime allocation) ----------
// pointer role table: 0=x 1=router_w 2=router_b 3=w1 4=w3 5=w2 6=sw1 7=sw3 8=sw2
__device__ const float* g_ptr[9];

__device__ __align__(16) float g_wt[WT_TOTAL];                  // 76 MB tf32-rounded
__device__ __align__(16) float g_gates[T_TOK * 2];
__device__ __align__(16) int   g_eidx[T_TOK * 2];
__device__ __align__(16) int   g_pos[T_TOK * 2];
__device__ __align__(16) int   g_counts[NE];
__device__ __align__(16) int   g_base[NE];
__device__ __align__(16) int   g_tok[NSLOT];
__device__ __align__(16) float g_slotgate[NSLOT];
__device__ __align__(16) float g_h[(size_t)NSLOT * HID];        // 16 MB (tf32-rounded)
__device__ __align__(16) float g_y[(size_t)NSLOT * DIM];        // 32 MB
__device__ __align__(16) float g_hsh[(size_t)NSH * T_TOK * HID];// 16 MB (tf32-rounded)
__device__ __align__(16) float g_ysh[(size_t)T_TOK * DIM];      // 16 MB

// ---------------- tf32 / cp.async helpers ----------------------------------
__device__ __forceinline__ uint32_t f2tf32(float f) {
    uint32_t u;
    asm("cvt.rna.tf32.f32 %0, %1;" : "=r"(u) : "f"(f));
    return u;
}
__device__ __forceinline__ float f2tf32f(float f) {
    return __uint_as_float(f2tf32(f));
}

__device__ __forceinline__ void mma_tf32(float c[4],
                                         uint32_t a0, uint32_t a1, uint32_t a2, uint32_t a3,
                                         uint32_t b0, uint32_t b1) {
    asm volatile(
        "mma.sync.aligned.m16n8k8.row.col.f32.tf32.tf32.f32 "
        "{%0,%1,%2,%3},{%4,%5,%6,%7},{%8,%9},{%0,%1,%2,%3};"
        : "+f"(c[0]), "+f"(c[1]), "+f"(c[2]), "+f"(c[3])
        : "r"(a0), "r"(a1), "r"(a2), "r"(a3), "r"(b0), "r"(b1));
}

__device__ __forceinline__ void cpa16(uint32_t smem_dst, const void* gsrc, int src_bytes) {
    asm volatile("cp.async.cg.shared.global [%0], [%1], 16, %2;"
                 :: "r"(smem_dst), "l"(gsrc), "r"(src_bytes));
}
__device__ __forceinline__ void cpa_commit() {
    asm volatile("cp.async.commit_group;");
}
template <int N>
__device__ __forceinline__ void cpa_wait() {
    asm volatile("cp.async.wait_group %0;" :: "n"(N));
}

// ---------------- input-role detection (content + size based) --------------
__global__ void detect_kernel(const float* p0, const float* p1, const float* p2,
                              const float* p3, const float* p4, const float* p5,
                              const float* p6, const float* p7, const float* p8,
                              long long s0, long long s1, long long s2,
                              long long s3, long long s4, long long s5,
                              long long s6, long long s7, long long s8) {
    if (threadIdx.x != 0 || blockIdx.x != 0) return;
    const float* p[9] = {p0, p1, p2, p3, p4, p5, p6, p7, p8};
    long long sz[9] = {s0, s1, s2, s3, s4, s5, s6, s7, s8};

    long long mn = sz[0];
    for (int i = 1; i < 9; i++) if (sz[i] < mn) mn = sz[i];
    long long unit = (mn == 32) ? 4 : 1;
    for (int i = 0; i < 9; i++) sz[i] /= unit;

    int pos_rb = -1, pos_rw = -1;
    int big[4]; int nb = 0;
    int med[3]; int nm = 0;
    for (int i = 0; i < 9; i++) {
        if (sz[i] == 8) pos_rb = i;
        else if (sz[i] == 8192) pos_rw = i;
        else if (sz[i] == 4194304) { if (nb < 4) big[nb] = i; nb++; }
        else if (sz[i] == 1048576) { if (nm < 3) med[nm] = i; nm++; }
    }

    bool ok = (pos_rb >= 0 && pos_rw >= 0 && nb == 4 && nm == 3);
    int pos_x = -1;
    if (ok) {
        for (int j = 0; j < 4 && pos_x < 0; j++) {
            float s = 0.f;
            const float* q = p[big[j]];
            for (int k = 0; k < 1024; k++) s += fabsf(q[k]);
            if (s * (1.f / 1024.f) > 0.1f) pos_x = big[j];
        }
        if (pos_x < 0) ok = false;
    }

    if (!ok) {
        g_ptr[0] = p[0]; g_ptr[1] = p[1]; g_ptr[2] = p[2];
        g_ptr[3] = p[3]; g_ptr[4] = p[4]; g_ptr[5] = p[5];
        g_ptr[6] = p[6]; g_ptr[7] = p[7]; g_ptr[8] = p[8];
        return;
    }

    int tr[3]; int nt = 0;
    for (int j = 0; j < 4; j++) if (big[j] != pos_x) tr[nt++] = big[j];

    g_ptr[0] = p[pos_x];
    g_ptr[1] = p[pos_rw];
    g_ptr[2] = p[pos_rb];
    if (pos_x == 0) {
        // dict-style: trios appear as (w1, w3, w2)
        g_ptr[3] = p[tr[0]]; g_ptr[4] = p[tr[1]]; g_ptr[5] = p[tr[2]];
        g_ptr[6] = p[med[0]]; g_ptr[7] = p[med[1]]; g_ptr[8] = p[med[2]];
    } else {
        // alpha-style: trios appear as (w1, w2, w3)
        g_ptr[3] = p[tr[0]]; g_ptr[4] = p[tr[2]]; g_ptr[5] = p[tr[1]];
        g_ptr[6] = p[med[0]]; g_ptr[7] = p[med[2]]; g_ptr[8] = p[med[1]];
    }
}

// ---------------- pre-convert x + all GEMM weights to tf32-rounded fp32 ----
__global__ void cvt_kernel() {
    long long i = (long long)blockIdx.x * blockDim.x + threadIdx.x;  // float4 idx
    if (i >= WT_TOTAL / 4) return;
    int role; long long b4;
    if      (i < 1048576) { role = 0; b4 = 0; }
    else if (i < 2097152) { role = 3; b4 = 1048576; }
    else if (i < 3145728) { role = 4; b4 = 2097152; }
    else if (i < 4194304) { role = 5; b4 = 3145728; }
    else if (i < 4456448) { role = 6; b4 = 4194304; }
    else if (i < 4718592) { role = 7; b4 = 4456448; }
    else                  { role = 8; b4 = 4718592; }
    float4 v = ((const float4*)g_ptr[role])[i - b4];
    float4 o;
    o.x = f2tf32f(v.x); o.y = f2tf32f(v.y);
    o.z = f2tf32f(v.z); o.w = f2tf32f(v.w);
    ((float4*)g_wt)[i] = o;
}

// ---------------- router: logits, top-2, softmax gates (pure fp32) ---------
__global__ void router_kernel() {
    const float* x  = g_ptr[0];
    const float* rw = g_ptr[1];
    const float* rb = g_ptr[2];
    int t = blockIdx.x * blockDim.y + threadIdx.y;
    if (t >= T_TOK) return;
    int lane = threadIdx.x;
    const float* xr = x + (size_t)t * DIM;

    float acc[NE];
#pragma unroll
    for (int e = 0; e < NE; e++) acc[e] = 0.f;
    for (int i = lane; i < DIM; i += 32) {
        float xv = xr[i];
        const float* w = rw + (size_t)i * NE;
#pragma unroll
        for (int e = 0; e < NE; e++) acc[e] += xv * w[e];
    }
#pragma unroll
    for (int e = 0; e < NE; e++) {
#pragma unroll
        for (int off = 16; off > 0; off >>= 1)
            acc[e] += __shfl_xor_sync(0xffffffffu, acc[e], off);
    }
    if (lane == 0) {
        float v[NE];
#pragma unroll
        for (int e = 0; e < NE; e++) v[e] = acc[e] + rb[e];
        int i0 = 0;
        for (int e = 1; e < NE; e++) if (v[e] > v[i0]) i0 = e;
        int i1 = (i0 == 0) ? 1 : 0;
        for (int e = 0; e < NE; e++) if (e != i0 && v[e] > v[i1]) i1 = e;
        float e1 = expf(v[i1] - v[i0]);
        float g0 = 1.f / (1.f + e1);
        float g1 = e1 * g0;
        g_gates[t * 2 + 0] = g0;
        g_gates[t * 2 + 1] = g1;
        g_eidx[t * 2 + 0] = i0;
        g_eidx[t * 2 + 1] = i1;
    }
}

// ---------------- deterministic gather with global slot packing ------------
__global__ void gather_kernel() {
    __shared__ int s_cnt[NE];
    __shared__ int s_base[NE];
    int wid = threadIdx.x / 32;
    int lane = threadIdx.x % 32;

    if (wid < NE) {
        int e = wid, cnt = 0;
        for (int chunk = 0; chunk < T_TOK; chunk += 32) {
            int t = chunk + lane;
            bool hit = (g_eidx[t * 2] == e) || (g_eidx[t * 2 + 1] == e);
            cnt += __popc(__ballot_sync(0xffffffffu, hit));
        }
        if (lane == 0) s_cnt[e] = cnt;
    }
    __syncthreads();
    if (threadIdx.x == 0) {
        int acc = 0;
        for (int e = 0; e < NE; e++) { s_base[e] = acc; acc += s_cnt[e]; }
    }
    __syncthreads();

    if (wid < NE) {
        int e = wid;
        int base = s_base[e];
        int run = 0;
        for (int chunk = 0; chunk < T_TOK; chunk += 32) {
            int t = chunk + lane;
            int k = -1;
            if (g_eidx[t * 2] == e) k = 0;
            else if (g_eidx[t * 2 + 1] == e) k = 1;
            unsigned mask = __ballot_sync(0xffffffffu, k >= 0);
            if (k >= 0) {
                int slot = base + run + __popc(mask & ((1u << lane) - 1u));
                g_tok[slot] = t;
                g_pos[t * 2 + k] = slot;
                g_slotgate[slot] = g_gates[t * 2 + k];
            }
            run += __popc(mask);
        }
        if (lane == 0) { g_counts[e] = run; g_base[e] = base; }
    }
}

// ---------------- GEMM1 (tf32 + cp.async double-buffer) --------------------
// block 128x64, BK=32, 8 warps (4x2), warp tile 32x32
// As [2][128][36] (m-major), Bs [2][32][72] (k-major)
#define G1_AS (128 * 36)
#define G1_BS (32 * 72)
#define G1_SMEM ((2 * G1_AS + 4 * G1_BS) * 4)

template <bool ROUTED>
__global__ void __launch_bounds__(256) gemm1_kernel() {
    extern __shared__ uint32_t sm[];
    int e = blockIdx.z;
    int cnt  = ROUTED ? g_counts[e] : T_TOK;
    int base = ROUTED ? g_base[e] : 0;
    int row0 = blockIdx.y * 128;
    if (row0 >= cnt) return;
    int h0 = blockIdx.x * 64;

    const float* xt = g_wt + OFF_X;
    const float* w1 = g_wt + (ROUTED ? OFF_W1 : OFF_SW1) + (size_t)e * DIM * HID;
    const float* w3 = g_wt + (ROUTED ? OFF_W3 : OFF_SW3) + (size_t)e * DIM * HID;
    float* hout = ROUTED ? (g_h + (size_t)base * HID)
                         : (g_hsh + (size_t)e * T_TOK * HID);
    const int* toklist = ROUTED ? (g_tok + base) : nullptr;

    uint32_t* As = sm;                       // 2 stages
    uint32_t* B1 = sm + 2 * G1_AS;
    uint32_t* B3 = B1 + 2 * G1_BS;
    uint32_t s_base_u = (uint32_t)__cvta_generic_to_shared(sm);

    int tid = threadIdx.x;
    int lrow = tid >> 1;
    int lkc  = (tid & 1) * 16;
    int r_l = row0 + lrow;
    const float* xrow = nullptr;
    if (r_l < cnt) { int tk = ROUTED ? toklist[r_l] : r_l; xrow = xt + (size_t)tk * DIM; }
    int lbk = tid >> 3;
    int lbn = (tid & 7) * 8;

    int wid = tid >> 5, lane = tid & 31;
    int wm = (wid >> 1) * 32;
    int wn = (wid & 1) * 32;
    int g = lane >> 2, tg = lane & 3;

    float acc1[2][4][4], acc3[2][4][4];
#pragma unroll
    for (int i = 0; i < 2; i++)
#pragma unroll
        for (int j = 0; j < 4; j++)
#pragma unroll
            for (int c = 0; c < 4; c++) { acc1[i][j][c] = 0.f; acc3[i][j][c] = 0.f; }

    auto issue = [&](int buf, int k0) {
        uint32_t a_dst = s_base_u + (uint32_t)(buf * G1_AS + lrow * 36 + lkc) * 4;
        const float* a_src = xrow ? (xrow + k0 + lkc) : xt;
        int ab = xrow ? 16 : 0;
#pragma unroll
        for (int c = 0; c < 4; c++)
            cpa16(a_dst + 16 * c, a_src + 4 * c, ab);
        uint32_t b1_dst = s_base_u + (uint32_t)(2 * G1_AS + buf * G1_BS + lbk * 72 + lbn) * 4;
        uint32_t b3_dst = s_base_u + (uint32_t)(2 * G1_AS + 2 * G1_BS + buf * G1_BS + lbk * 72 + lbn) * 4;
        const float* b1_src = w1 + (size_t)(k0 + lbk) * HID + h0 + lbn;
        const float* b3_src = w3 + (size_t)(k0 + lbk) * HID + h0 + lbn;
        cpa16(b1_dst,      b1_src,     16);
        cpa16(b1_dst + 16, b1_src + 4, 16);
        cpa16(b3_dst,      b3_src,     16);
        cpa16(b3_dst + 16, b3_src + 4, 16);
        cpa_commit();
    };

    issue(0, 0);
    int buf = 0;
    for (int k0 = 0; k0 < DIM; k0 += 32) {
        bool has_next = (k0 + 32 < DIM);
        if (has_next) { issue(buf ^ 1, k0 + 32); cpa_wait<1>(); }
        else          { cpa_wait<0>(); }
        __syncthreads();
        const uint32_t* Ab  = As + buf * G1_AS;
        const uint32_t* B1b = B1 + buf * G1_BS;
        const uint32_t* B3b = B3 + buf * G1_BS;
#pragma unroll
        for (int kk = 0; kk < 32; kk += 8) {
            uint32_t a[2][4];
#pragma unroll
            for (int i = 0; i < 2; i++) {
                int m = wm + i * 16 + g;
                a[i][0] = Ab[m * 36 + kk + tg];
                a[i][1] = Ab[(m + 8) * 36 + kk + tg];
                a[i][2] = Ab[m * 36 + kk + tg + 4];
                a[i][3] = Ab[(m + 8) * 36 + kk + tg + 4];
            }
#pragma unroll
            for (int j = 0; j < 4; j++) {
                int n = wn + j * 8 + g;
                uint32_t p0 = B1b[(kk + tg) * 72 + n];
                uint32_t p1 = B1b[(kk + tg + 4) * 72 + n];
                uint32_t q0 = B3b[(kk + tg) * 72 + n];
                uint32_t q1 = B3b[(kk + tg + 4) * 72 + n];
#pragma unroll
                for (int i = 0; i < 2; i++) {
                    mma_tf32(acc1[i][j], a[i][0], a[i][1], a[i][2], a[i][3], p0, p1);
                    mma_tf32(acc3[i][j], a[i][0], a[i][1], a[i][2], a[i][3], q0, q1);
                }
            }
        }
        __syncthreads();
        buf ^= 1;
    }

#pragma unroll
    for (int i = 0; i < 2; i++) {
        int r0 = row0 + wm + i * 16 + g;
        int r1 = r0 + 8;
#pragma unroll
        for (int j = 0; j < 4; j++) {
            int c = h0 + wn + j * 8 + 2 * tg;
            if (r0 < cnt) {
                float v0 = acc1[i][j][0], v1 = acc1[i][j][1];
                float2 o;
                o.x = f2tf32f((v0 / (1.f + expf(-v0))) * acc3[i][j][0]);
                o.y = f2tf32f((v1 / (1.f + expf(-v1))) * acc3[i][j][1]);
                *(float2*)(hout + (size_t)r0 * HID + c) = o;
            }
            if (r1 < cnt) {
                float v2 = acc1[i][j][2], v3 = acc1[i][j][3];
                float2 o;
                o.x = f2tf32f((v2 / (1.f + expf(-v2))) * acc3[i][j][2]);
                o.y = f2tf32f((v3 / (1.f + expf(-v3))) * acc3[i][j][3]);
                *(float2*)(hout + (size_t)r1 * HID + c) = o;
            }
        }
    }
}

// ---------------- GEMM2 (tf32 + cp.async double-buffer) --------------------
#define G2_AS (128 * 36)
#define G2_BS (32 * 72)
#define G2_SMEM ((2 * G2_AS + 2 * G2_BS) * 4)

template <bool ROUTED>
__global__ void __launch_bounds__(256) gemm2_kernel() {
    extern __shared__ uint32_t sm[];
    int e = blockIdx.z;
    int cnt  = ROUTED ? g_counts[e] : T_TOK;
    int base = ROUTED ? g_base[e] : 0;
    int row0 = blockIdx.y * 128;
    if (row0 >= cnt) return;
    int d0 = blockIdx.x * 64;

    float* y = ROUTED ? (g_y + (size_t)base * DIM) : g_ysh;

    uint32_t* As = sm;
    uint32_t* Bs = sm + 2 * G2_AS;
    uint32_t s_base_u = (uint32_t)__cvta_generic_to_shared(sm);

    int tid = threadIdx.x;
    int lrow = tid >> 1;
    int lkc  = (tid & 1) * 16;
    int r_l = row0 + lrow;
    int lbk = tid >> 3;
    int lbn = (tid & 7) * 8;

    int wid = tid >> 5, lane = tid & 31;
    int wm = (wid >> 1) * 32;
    int wn = (wid & 1) * 32;
    int g = lane >> 2, tg = lane & 3;

    float acc[2][4][4];
#pragma unroll
    for (int i = 0; i < 2; i++)
#pragma unroll
        for (int j = 0; j < 4; j++)
#pragma unroll
            for (int c = 0; c < 4; c++) acc[i][j][c] = 0.f;

    int total_k = (ROUTED ? 1 : NSH) * HID;

    auto issue = [&](int buf, int k0) {
        int s = k0 >> 9;            // segment (shared expert index)
        int kl = k0 & (HID - 1);
        const float* A = ROUTED ? (g_h + (size_t)base * HID)
                                : (g_hsh + (size_t)s * T_TOK * HID);
        const float* w2 = g_wt + (ROUTED ? OFF_W2 : OFF_SW2)
                        + (size_t)(ROUTED ? e : s) * HID * DIM;
        uint32_t a_dst = s_base_u + (uint32_t)(buf * G2_AS + lrow * 36 + lkc) * 4;
        const float* a_src = (r_l < cnt) ? (A + (size_t)r_l * HID + kl + lkc) : A;
        int ab = (r_l < cnt) ? 16 : 0;
#pragma unroll
        for (int c = 0; c < 4; c++)
            cpa16(a_dst + 16 * c, a_src + 4 * c, ab);
        uint32_t b_dst = s_base_u + (uint32_t)(2 * G2_AS + buf * G2_BS + lbk * 72 + lbn) * 4;
        const float* b_src = w2 + (size_t)(kl + lbk) * DIM + d0 + lbn;
        cpa16(b_dst,      b_src,     16);
        cpa16(b_dst + 16, b_src + 4, 16);
        cpa_commit();
    };

    issue(0, 0);
    int buf = 0;
    for (int k0 = 0; k0 < total_k; k0 += 32) {
        bool has_next = (k0 + 32 < total_k);
        if (has_next) { issue(buf ^ 1, k0 + 32); cpa_wait<1>(); }
        else          { cpa_wait<0>(); }
        __syncthreads();
        const uint32_t* Ab = As + buf * G2_AS;
        const uint32_t* Bb = Bs + buf * G2_BS;
#pragma unroll
        for (int kk = 0; kk < 32; kk += 8) {
            uint32_t a[2][4];
#pragma unroll
            for (int i = 0; i < 2; i++) {
                int m = wm + i * 16 + g;
                a[i][0] = Ab[m * 36 + kk + tg];
                a[i][1] = Ab[(m + 8) * 36 + kk + tg];
                a[i][2] = Ab[m * 36 + kk + tg + 4];
                a[i][3] = Ab[(m + 8) * 36 + kk + tg + 4];
            }
#pragma unroll
            for (int j = 0; j < 4; j++) {
                int n = wn + j * 8 + g;
                uint32_t p0 = Bb[(kk + tg) * 72 + n];
                uint32_t p1 = Bb[(kk + tg + 4) * 72 + n];
#pragma unroll
                for (int i = 0; i < 2; i++)
                    mma_tf32(acc[i][j], a[i][0], a[i][1], a[i][2], a[i][3], p0, p1);
            }
        }
        __syncthreads();
        buf ^= 1;
    }

#pragma unroll
    for (int i = 0; i < 2; i++) {
        int r0 = row0 + wm + i * 16 + g;
        int r1 = r0 + 8;
        float sc0 = (ROUTED && r0 < cnt) ? g_slotgate[base + r0] : 1.f;
        float sc1 = (ROUTED && r1 < cnt) ? g_slotgate[base + r1] : 1.f;
#pragma unroll
        for (int j = 0; j < 4; j++) {
            int c = d0 + wn + j * 8 + 2 * tg;
            if (r0 < cnt) {
                float2 o;
                o.x = acc[i][j][0] * sc0;
                o.y = acc[i][j][1] * sc0;
                *(float2*)(y + (size_t)r0 * DIM + c) = o;
            }
            if (r1 < cnt) {
                float2 o;
                o.x = acc[i][j][2] * sc1;
                o.y = acc[i][j][3] * sc1;
                *(float2*)(y + (size_t)r1 * DIM + c) = o;
            }
        }
    }
}

// ---------------- combine: out = shared + y[slot0] + y[slot1] --------------
__global__ void combine_kernel(float* __restrict__ out) {
    int idx = blockIdx.x * blockDim.x + threadIdx.x;   // over T*DIM/4
    int t  = idx / (DIM / 4);
    int d4 = idx % (DIM / 4);
    int p0 = g_pos[t * 2 + 0];
    int p1 = g_pos[t * 2 + 1];
    float4 a = ((const float4*)(g_ysh + (size_t)t * DIM))[d4];
    float4 b = ((const float4*)(g_y + (size_t)p0 * DIM))[d4];
    float4 c = ((const float4*)(g_y + (size_t)p1 * DIM))[d4];
    float4 o;
    o.x = a.x + b.x + c.x;
    o.y = a.y + b.y + c.y;
    o.z = a.z + b.z + c.z;
    o.w = a.w + b.w + c.w;
    ((float4*)out)[idx] = o;
}

// ---------------- launcher --------------------------------------------------
extern "C" void kernel_launch(void* const* d_in, const int* in_sizes, int n_in,
                              void* d_out, int out_size) {
    static bool attr_done = false;
    if (!attr_done) {
        cudaFuncSetAttribute(gemm1_kernel<true>,
                             cudaFuncAttributeMaxDynamicSharedMemorySize, G1_SMEM);
        cudaFuncSetAttribute(gemm1_kernel<false>,
                             cudaFuncAttributeMaxDynamicSharedMemorySize, G1_SMEM);
        cudaFuncSetAttribute(gemm2_kernel<true>,
                             cudaFuncAttributeMaxDynamicSharedMemorySize, G2_SMEM);
        cudaFuncSetAttribute(gemm2_kernel<false>,
                             cudaFuncAttributeMaxDynamicSharedMemorySize, G2_SMEM);
        attr_done = true;
    }

    detect_kernel<<<1, 32>>>(
        (const float*)d_in[0], (const float*)d_in[1], (const float*)d_in[2],
        (const float*)d_in[3], (const float*)d_in[4], (const float*)d_in[5],
        (const float*)d_in[6], (const float*)d_in[7], (const float*)d_in[8],
        (long long)in_sizes[0], (long long)in_sizes[1], (long long)in_sizes[2],
        (long long)in_sizes[3], (long long)in_sizes[4], (long long)in_sizes[5],
        (long long)in_sizes[6], (long long)in_sizes[7], (long long)in_sizes[8]);

    cvt_kernel<<<(WT_TOTAL / 4 + 255) / 256, 256>>>();
    router_kernel<<<T_TOK / 4, dim3(32, 4)>>>();
    gather_kernel<<<1, NE * 32>>>();

    // routed experts on gathered rows
    gemm1_kernel<true><<<dim3(HID / 64, T_TOK / 128, NE), 256, G1_SMEM>>>();
    gemm2_kernel<true><<<dim3(DIM / 64, T_TOK / 128, NE), 256, G2_SMEM>>>();

    // shared experts (dense over all tokens)
    gemm1_kernel<false><<<dim3(HID / 64, T_TOK / 128, NSH), 256, G1_SMEM>>>();
    gemm2_kernel<false><<<dim3(DIM / 64, T_TOK / 128, 1), 256, G2_SMEM>>>();

    combine_kernel<<<(T_TOK * DIM / 4) / 256, 256>>>((float*)d_out);
}

// round 8
// speedup vs baseline: 2.2890x; 1.0557x over previous
#include <cuda_runtime.h>
#include <math.h>
#include <stdint.h>

#define T_TOK 4096
#define DIM   1024
#define HID   512
#define NE    8
#define NSH   2
#define NSLOT (2 * T_TOK)

// offsets (floats) inside g_wt pre-converted scratch
#define OFF_X   0
#define OFF_W1  4194304
#define OFF_W3  8388608
#define OFF_W2  12582912
#define OFF_SW1 16777216
#define OFF_SW3 17825792
#define OFF_SW2 18874368
#define WT_TOTAL 19922944   // floats (76 MB)

// ---------------- scratch (device globals; no runtime allocation) ----------
// pointer role table: 0=x 1=router_w 2=router_b 3=w1 4=w3 5=w2 6=sw1 7=sw3 8=sw2
__device__ const float* g_ptr[9];

__device__ __align__(16) float g_wt[WT_TOTAL];                  // 76 MB tf32-rounded
__device__ __align__(16) float g_gates[T_TOK * 2];
__device__ __align__(16) int   g_eidx[T_TOK * 2];
__device__ __align__(16) int   g_pos[T_TOK * 2];
__device__ __align__(16) int   g_counts[NE];
__device__ __align__(16) int   g_base[NE];
__device__ __align__(16) int   g_tok[NSLOT];
__device__ __align__(16) float g_slotgate[NSLOT];
__device__ __align__(16) float g_h[(size_t)NSLOT * HID];        // 16 MB (tf32-rounded)
__device__ __align__(16) float g_y[(size_t)NSLOT * DIM];        // 32 MB
__device__ __align__(16) float g_hsh[(size_t)NSH * T_TOK * HID];// 16 MB (tf32-rounded)

// ---------------- tf32 / cp.async helpers ----------------------------------
__device__ __forceinline__ uint32_t f2tf32(float f) {
    uint32_t u;
    asm("cvt.rna.tf32.f32 %0, %1;" : "=r"(u) : "f"(f));
    return u;
}
__device__ __forceinline__ float f2tf32f(float f) {
    return __uint_as_float(f2tf32(f));
}

__device__ __forceinline__ void mma_tf32(float c[4],
                                         uint32_t a0, uint32_t a1, uint32_t a2, uint32_t a3,
                                         uint32_t b0, uint32_t b1) {
    asm volatile(
        "mma.sync.aligned.m16n8k8.row.col.f32.tf32.tf32.f32 "
        "{%0,%1,%2,%3},{%4,%5,%6,%7},{%8,%9},{%0,%1,%2,%3};"
        : "+f"(c[0]), "+f"(c[1]), "+f"(c[2]), "+f"(c[3])
        : "r"(a0), "r"(a1), "r"(a2), "r"(a3), "r"(b0), "r"(b1));
}

__device__ __forceinline__ void cpa16(uint32_t smem_dst, const void* gsrc, int src_bytes) {
    asm volatile("cp.async.cg.shared.global [%0], [%1], 16, %2;"
                 :: "r"(smem_dst), "l"(gsrc), "r"(src_bytes));
}
__device__ __forceinline__ void cpa_commit() {
    asm volatile("cp.async.commit_group;");
}
template <int N>
__device__ __forceinline__ void cpa_wait() {
    asm volatile("cp.async.wait_group %0;" :: "n"(N));
}

// ---------------- input-role detection (content + size based) --------------
__global__ void detect_kernel(const float* p0, const float* p1, const float* p2,
                              const float* p3, const float* p4, const float* p5,
                              const float* p6, const float* p7, const float* p8,
                              long long s0, long long s1, long long s2,
                              long long s3, long long s4, long long s5,
                              long long s6, long long s7, long long s8) {
    if (threadIdx.x != 0 || blockIdx.x != 0) return;
    const float* p[9] = {p0, p1, p2, p3, p4, p5, p6, p7, p8};
    long long sz[9] = {s0, s1, s2, s3, s4, s5, s6, s7, s8};

    long long mn = sz[0];
    for (int i = 1; i < 9; i++) if (sz[i] < mn) mn = sz[i];
    long long unit = (mn == 32) ? 4 : 1;
    for (int i = 0; i < 9; i++) sz[i] /= unit;

    int pos_rb = -1, pos_rw = -1;
    int big[4]; int nb = 0;
    int med[3]; int nm = 0;
    for (int i = 0; i < 9; i++) {
        if (sz[i] == 8) pos_rb = i;
        else if (sz[i] == 8192) pos_rw = i;
        else if (sz[i] == 4194304) { if (nb < 4) big[nb] = i; nb++; }
        else if (sz[i] == 1048576) { if (nm < 3) med[nm] = i; nm++; }
    }

    bool ok = (pos_rb >= 0 && pos_rw >= 0 && nb == 4 && nm == 3);
    int pos_x = -1;
    if (ok) {
        for (int j = 0; j < 4 && pos_x < 0; j++) {
            float s = 0.f;
            const float* q = p[big[j]];
            for (int k = 0; k < 1024; k++) s += fabsf(q[k]);
            if (s * (1.f / 1024.f) > 0.1f) pos_x = big[j];
        }
        if (pos_x < 0) ok = false;
    }

    if (!ok) {
        g_ptr[0] = p[0]; g_ptr[1] = p[1]; g_ptr[2] = p[2];
        g_ptr[3] = p[3]; g_ptr[4] = p[4]; g_ptr[5] = p[5];
        g_ptr[6] = p[6]; g_ptr[7] = p[7]; g_ptr[8] = p[8];
        return;
    }

    int tr[3]; int nt = 0;
    for (int j = 0; j < 4; j++) if (big[j] != pos_x) tr[nt++] = big[j];

    g_ptr[0] = p[pos_x];
    g_ptr[1] = p[pos_rw];
    g_ptr[2] = p[pos_rb];
    if (pos_x == 0) {
        // dict-style: trios appear as (w1, w3, w2)
        g_ptr[3] = p[tr[0]]; g_ptr[4] = p[tr[1]]; g_ptr[5] = p[tr[2]];
        g_ptr[6] = p[med[0]]; g_ptr[7] = p[med[1]]; g_ptr[8] = p[med[2]];
    } else {
        // alpha-style: trios appear as (w1, w2, w3)
        g_ptr[3] = p[tr[0]]; g_ptr[4] = p[tr[2]]; g_ptr[5] = p[tr[1]];
        g_ptr[6] = p[med[0]]; g_ptr[7] = p[med[2]]; g_ptr[8] = p[med[1]];
    }
}

// ---------------- pre-convert x + all GEMM weights to tf32-rounded fp32 ----
__global__ void cvt_kernel() {
    long long i = (long long)blockIdx.x * blockDim.x + threadIdx.x;  // float4 idx
    if (i >= WT_TOTAL / 4) return;
    int role; long long b4;
    if      (i < 1048576) { role = 0; b4 = 0; }
    else if (i < 2097152) { role = 3; b4 = 1048576; }
    else if (i < 3145728) { role = 4; b4 = 2097152; }
    else if (i < 4194304) { role = 5; b4 = 3145728; }
    else if (i < 4456448) { role = 6; b4 = 4194304; }
    else if (i < 4718592) { role = 7; b4 = 4456448; }
    else                  { role = 8; b4 = 4718592; }
    float4 v = ((const float4*)g_ptr[role])[i - b4];
    float4 o;
    o.x = f2tf32f(v.x); o.y = f2tf32f(v.y);
    o.z = f2tf32f(v.z); o.w = f2tf32f(v.w);
    ((float4*)g_wt)[i] = o;
}

// ---------------- router: logits, top-2, softmax gates (pure fp32) ---------
__global__ void router_kernel() {
    const float* x  = g_ptr[0];
    const float* rw = g_ptr[1];
    const float* rb = g_ptr[2];
    int t = blockIdx.x * blockDim.y + threadIdx.y;
    if (t >= T_TOK) return;
    int lane = threadIdx.x;
    const float* xr = x + (size_t)t * DIM;

    float acc[NE];
#pragma unroll
    for (int e = 0; e < NE; e++) acc[e] = 0.f;
    for (int i = lane; i < DIM; i += 32) {
        float xv = xr[i];
        const float* w = rw + (size_t)i * NE;
#pragma unroll
        for (int e = 0; e < NE; e++) acc[e] += xv * w[e];
    }
#pragma unroll
    for (int e = 0; e < NE; e++) {
#pragma unroll
        for (int off = 16; off > 0; off >>= 1)
            acc[e] += __shfl_xor_sync(0xffffffffu, acc[e], off);
    }
    if (lane == 0) {
        float v[NE];
#pragma unroll
        for (int e = 0; e < NE; e++) v[e] = acc[e] + rb[e];
        int i0 = 0;
        for (int e = 1; e < NE; e++) if (v[e] > v[i0]) i0 = e;
        int i1 = (i0 == 0) ? 1 : 0;
        for (int e = 0; e < NE; e++) if (e != i0 && v[e] > v[i1]) i1 = e;
        float e1 = expf(v[i1] - v[i0]);
        float g0 = 1.f / (1.f + e1);
        float g1 = e1 * g0;
        g_gates[t * 2 + 0] = g0;
        g_gates[t * 2 + 1] = g1;
        g_eidx[t * 2 + 0] = i0;
        g_eidx[t * 2 + 1] = i1;
    }
}

// ---------------- smem-resident deterministic gather -----------------------
__global__ void __launch_bounds__(1024) gather_kernel() {
    __shared__ int   se[T_TOK * 2];     // 32 KB
    __shared__ float sg[T_TOK * 2];     // 32 KB
    __shared__ int   s_cnt[NE];
    __shared__ int   s_base[NE];
    int tid = threadIdx.x;

    for (int i = tid; i < T_TOK * 2; i += 1024) {
        se[i] = g_eidx[i];
        sg[i] = g_gates[i];
    }
    __syncthreads();

    int wid = tid >> 5;
    int lane = tid & 31;

    if (wid < NE) {
        int e = wid, cnt = 0;
        for (int chunk = 0; chunk < T_TOK; chunk += 32) {
            int t = chunk + lane;
            bool hit = (se[t * 2] == e) || (se[t * 2 + 1] == e);
            cnt += __popc(__ballot_sync(0xffffffffu, hit));
        }
        if (lane == 0) s_cnt[e] = cnt;
    }
    __syncthreads();
    if (tid == 0) {
        int acc = 0;
        for (int e = 0; e < NE; e++) { s_base[e] = acc; acc += s_cnt[e]; }
    }
    __syncthreads();

    if (wid < NE) {
        int e = wid;
        int base = s_base[e];
        int run = 0;
        for (int chunk = 0; chunk < T_TOK; chunk += 32) {
            int t = chunk + lane;
            int k = -1;
            if (se[t * 2] == e) k = 0;
            else if (se[t * 2 + 1] == e) k = 1;
            unsigned mask = __ballot_sync(0xffffffffu, k >= 0);
            if (k >= 0) {
                int slot = base + run + __popc(mask & ((1u << lane) - 1u));
                g_tok[slot] = t;
                g_pos[t * 2 + k] = slot;
                g_slotgate[slot] = sg[t * 2 + k];
            }
            run += __popc(mask);
        }
        if (lane == 0) { g_counts[e] = run; g_base[e] = base; }
    }
}

// ---------------- GEMM1 (tf32 + cp.async double-buffer) --------------------
// block 128x64, BK=32, 8 warps (4x2), warp tile 32x32
// As [2][128][36] (m-major), Bs [2][32][72] (k-major)
#define G1_AS (128 * 36)
#define G1_BS (32 * 72)
#define G1_SMEM ((2 * G1_AS + 4 * G1_BS) * 4)

template <bool ROUTED>
__global__ void __launch_bounds__(256) gemm1_kernel() {
    extern __shared__ uint32_t sm[];
    int e = blockIdx.z;
    int cnt  = ROUTED ? g_counts[e] : T_TOK;
    int base = ROUTED ? g_base[e] : 0;
    int row0 = blockIdx.y * 128;
    if (row0 >= cnt) return;
    int h0 = blockIdx.x * 64;

    const float* xt = g_wt + OFF_X;
    const float* w1 = g_wt + (ROUTED ? OFF_W1 : OFF_SW1) + (size_t)e * DIM * HID;
    const float* w3 = g_wt + (ROUTED ? OFF_W3 : OFF_SW3) + (size_t)e * DIM * HID;
    float* hout = ROUTED ? (g_h + (size_t)base * HID)
                         : (g_hsh + (size_t)e * T_TOK * HID);
    const int* toklist = ROUTED ? (g_tok + base) : nullptr;

    uint32_t* As = sm;                       // 2 stages
    uint32_t* B1 = sm + 2 * G1_AS;
    uint32_t* B3 = B1 + 2 * G1_BS;
    uint32_t s_base_u = (uint32_t)__cvta_generic_to_shared(sm);

    int tid = threadIdx.x;
    int lrow = tid >> 1;
    int lkc  = (tid & 1) * 16;
    int r_l = row0 + lrow;
    const float* xrow = nullptr;
    if (r_l < cnt) { int tk = ROUTED ? toklist[r_l] : r_l; xrow = xt + (size_t)tk * DIM; }
    int lbk = tid >> 3;
    int lbn = (tid & 7) * 8;

    int wid = tid >> 5, lane = tid & 31;
    int wm = (wid >> 1) * 32;
    int wn = (wid & 1) * 32;
    int g = lane >> 2, tg = lane & 3;

    float acc1[2][4][4], acc3[2][4][4];
#pragma unroll
    for (int i = 0; i < 2; i++)
#pragma unroll
        for (int j = 0; j < 4; j++)
#pragma unroll
            for (int c = 0; c < 4; c++) { acc1[i][j][c] = 0.f; acc3[i][j][c] = 0.f; }

    auto issue = [&](int buf, int k0) {
        uint32_t a_dst = s_base_u + (uint32_t)(buf * G1_AS + lrow * 36 + lkc) * 4;
        const float* a_src = xrow ? (xrow + k0 + lkc) : xt;
        int ab = xrow ? 16 : 0;
#pragma unroll
        for (int c = 0; c < 4; c++)
            cpa16(a_dst + 16 * c, a_src + 4 * c, ab);
        uint32_t b1_dst = s_base_u + (uint32_t)(2 * G1_AS + buf * G1_BS + lbk * 72 + lbn) * 4;
        uint32_t b3_dst = s_base_u + (uint32_t)(2 * G1_AS + 2 * G1_BS + buf * G1_BS + lbk * 72 + lbn) * 4;
        const float* b1_src = w1 + (size_t)(k0 + lbk) * HID + h0 + lbn;
        const float* b3_src = w3 + (size_t)(k0 + lbk) * HID + h0 + lbn;
        cpa16(b1_dst,      b1_src,     16);
        cpa16(b1_dst + 16, b1_src + 4, 16);
        cpa16(b3_dst,      b3_src,     16);
        cpa16(b3_dst + 16, b3_src + 4, 16);
        cpa_commit();
    };

    issue(0, 0);
    int buf = 0;
    for (int k0 = 0; k0 < DIM; k0 += 32) {
        bool has_next = (k0 + 32 < DIM);
        if (has_next) { issue(buf ^ 1, k0 + 32); cpa_wait<1>(); }
        else          { cpa_wait<0>(); }
        __syncthreads();
        const uint32_t* Ab  = As + buf * G1_AS;
        const uint32_t* B1b = B1 + buf * G1_BS;
        const uint32_t* B3b = B3 + buf * G1_BS;
#pragma unroll
        for (int kk = 0; kk < 32; kk += 8) {
            uint32_t a[2][4];
#pragma unroll
            for (int i = 0; i < 2; i++) {
                int m = wm + i * 16 + g;
                a[i][0] = Ab[m * 36 + kk + tg];
                a[i][1] = Ab[(m + 8) * 36 + kk + tg];
                a[i][2] = Ab[m * 36 + kk + tg + 4];
                a[i][3] = Ab[(m + 8) * 36 + kk + tg + 4];
            }
#pragma unroll
            for (int j = 0; j < 4; j++) {
                int n = wn + j * 8 + g;
                uint32_t p0 = B1b[(kk + tg) * 72 + n];
                uint32_t p1 = B1b[(kk + tg + 4) * 72 + n];
                uint32_t q0 = B3b[(kk + tg) * 72 + n];
                uint32_t q1 = B3b[(kk + tg + 4) * 72 + n];
#pragma unroll
                for (int i = 0; i < 2; i++) {
                    mma_tf32(acc1[i][j], a[i][0], a[i][1], a[i][2], a[i][3], p0, p1);
                    mma_tf32(acc3[i][j], a[i][0], a[i][1], a[i][2], a[i][3], q0, q1);
                }
            }
        }
        __syncthreads();
        buf ^= 1;
    }

#pragma unroll
    for (int i = 0; i < 2; i++) {
        int r0 = row0 + wm + i * 16 + g;
        int r1 = r0 + 8;
#pragma unroll
        for (int j = 0; j < 4; j++) {
            int c = h0 + wn + j * 8 + 2 * tg;
            if (r0 < cnt) {
                float v0 = acc1[i][j][0], v1 = acc1[i][j][1];
                float2 o;
                o.x = f2tf32f((v0 / (1.f + expf(-v0))) * acc3[i][j][0]);
                o.y = f2tf32f((v1 / (1.f + expf(-v1))) * acc3[i][j][1]);
                *(float2*)(hout + (size_t)r0 * HID + c) = o;
            }
            if (r1 < cnt) {
                float v2 = acc1[i][j][2], v3 = acc1[i][j][3];
                float2 o;
                o.x = f2tf32f((v2 / (1.f + expf(-v2))) * acc3[i][j][2]);
                o.y = f2tf32f((v3 / (1.f + expf(-v3))) * acc3[i][j][3]);
                *(float2*)(hout + (size_t)r1 * HID + c) = o;
            }
        }
    }
}

// ---------------- GEMM2 (tf32 + cp.async double-buffer) --------------------
// ROUTED: y[slot] = (h @ w2) * gate  -> g_y
// !ROUTED: out[t] = sum_s(hsh_s @ sw2_s) + g_y[slot0(t)] + g_y[slot1(t)]  (fused combine)
#define G2_AS (128 * 36)
#define G2_BS (32 * 72)
#define G2_SMEM ((2 * G2_AS + 2 * G2_BS) * 4)

template <bool ROUTED>
__global__ void __launch_bounds__(256) gemm2_kernel(float* __restrict__ out) {
    extern __shared__ uint32_t sm[];
    int e = blockIdx.z;
    int cnt  = ROUTED ? g_counts[e] : T_TOK;
    int base = ROUTED ? g_base[e] : 0;
    int row0 = blockIdx.y * 128;
    if (row0 >= cnt) return;
    int d0 = blockIdx.x * 64;

    uint32_t* As = sm;
    uint32_t* Bs = sm + 2 * G2_AS;
    uint32_t s_base_u = (uint32_t)__cvta_generic_to_shared(sm);

    int tid = threadIdx.x;
    int lrow = tid >> 1;
    int lkc  = (tid & 1) * 16;
    int r_l = row0 + lrow;
    int lbk = tid >> 3;
    int lbn = (tid & 7) * 8;

    int wid = tid >> 5, lane = tid & 31;
    int wm = (wid >> 1) * 32;
    int wn = (wid & 1) * 32;
    int g = lane >> 2, tg = lane & 3;

    float acc[2][4][4];
#pragma unroll
    for (int i = 0; i < 2; i++)
#pragma unroll
        for (int j = 0; j < 4; j++)
#pragma unroll
            for (int c = 0; c < 4; c++) acc[i][j][c] = 0.f;

    int total_k = (ROUTED ? 1 : NSH) * HID;

    auto issue = [&](int buf, int k0) {
        int s = k0 >> 9;            // segment (shared expert index)
        int kl = k0 & (HID - 1);
        const float* A = ROUTED ? (g_h + (size_t)base * HID)
                                : (g_hsh + (size_t)s * T_TOK * HID);
        const float* w2 = g_wt + (ROUTED ? OFF_W2 : OFF_SW2)
                        + (size_t)(ROUTED ? e : s) * HID * DIM;
        uint32_t a_dst = s_base_u + (uint32_t)(buf * G2_AS + lrow * 36 + lkc) * 4;
        const float* a_src = (r_l < cnt) ? (A + (size_t)r_l * HID + kl + lkc) : A;
        int ab = (r_l < cnt) ? 16 : 0;
#pragma unroll
        for (int c = 0; c < 4; c++)
            cpa16(a_dst + 16 * c, a_src + 4 * c, ab);
        uint32_t b_dst = s_base_u + (uint32_t)(2 * G2_AS + buf * G2_BS + lbk * 72 + lbn) * 4;
        const float* b_src = w2 + (size_t)(kl + lbk) * DIM + d0 + lbn;
        cpa16(b_dst,      b_src,     16);
        cpa16(b_dst + 16, b_src + 4, 16);
        cpa_commit();
    };

    issue(0, 0);
    int buf = 0;
    for (int k0 = 0; k0 < total_k; k0 += 32) {
        bool has_next = (k0 + 32 < total_k);
        if (has_next) { issue(buf ^ 1, k0 + 32); cpa_wait<1>(); }
        else          { cpa_wait<0>(); }
        __syncthreads();
        const uint32_t* Ab = As + buf * G2_AS;
        const uint32_t* Bb = Bs + buf * G2_BS;
#pragma unroll
        for (int kk = 0; kk < 32; kk += 8) {
            uint32_t a[2][4];
#pragma unroll
            for (int i = 0; i < 2; i++) {
                int m = wm + i * 16 + g;
                a[i][0] = Ab[m * 36 + kk + tg];
                a[i][1] = Ab[(m + 8) * 36 + kk + tg];
                a[i][2] = Ab[m * 36 + kk + tg + 4];
                a[i][3] = Ab[(m + 8) * 36 + kk + tg + 4];
            }
#pragma unroll
            for (int j = 0; j < 4; j++) {
                int n = wn + j * 8 + g;
                uint32_t p0 = Bb[(kk + tg) * 72 + n];
                uint32_t p1 = Bb[(kk + tg + 4) * 72 + n];
#pragma unroll
                for (int i = 0; i < 2; i++)
                    mma_tf32(acc[i][j], a[i][0], a[i][1], a[i][2], a[i][3], p0, p1);
            }
        }
        __syncthreads();
        buf ^= 1;
    }

#pragma unroll
    for (int i = 0; i < 2; i++) {
        int r0 = row0 + wm + i * 16 + g;
        int r1 = r0 + 8;
        if (ROUTED) {
            float sc0 = (r0 < cnt) ? g_slotgate[base + r0] : 1.f;
            float sc1 = (r1 < cnt) ? g_slotgate[base + r1] : 1.f;
#pragma unroll
            for (int j = 0; j < 4; j++) {
                int c = d0 + wn + j * 8 + 2 * tg;
                if (r0 < cnt) {
                    float2 o;
                    o.x = acc[i][j][0] * sc0;
                    o.y = acc[i][j][1] * sc0;
                    *(float2*)(g_y + (size_t)(base + r0) * DIM + c) = o;
                }
                if (r1 < cnt) {
                    float2 o;
                    o.x = acc[i][j][2] * sc1;
                    o.y = acc[i][j][3] * sc1;
                    *(float2*)(g_y + (size_t)(base + r1) * DIM + c) = o;
                }
            }
        } else {
            // fused combine: out = shared_sum + routed slot contributions
            int p00 = g_pos[r0 * 2 + 0], p01 = g_pos[r0 * 2 + 1];
            int p10 = g_pos[r1 * 2 + 0], p11 = g_pos[r1 * 2 + 1];
#pragma unroll
            for (int j = 0; j < 4; j++) {
                int c = d0 + wn + j * 8 + 2 * tg;
                float2 a0 = *(const float2*)(g_y + (size_t)p00 * DIM + c);
                float2 a1 = *(const float2*)(g_y + (size_t)p01 * DIM + c);
                float2 b0 = *(const float2*)(g_y + (size_t)p10 * DIM + c);
                float2 b1 = *(const float2*)(g_y + (size_t)p11 * DIM + c);
                float2 o0, o1;
                o0.x = acc[i][j][0] + a0.x + a1.x;
                o0.y = acc[i][j][1] + a0.y + a1.y;
                o1.x = acc[i][j][2] + b0.x + b1.x;
                o1.y = acc[i][j][3] + b0.y + b1.y;
                *(float2*)(out + (size_t)r0 * DIM + c) = o0;
                *(float2*)(out + (size_t)r1 * DIM + c) = o1;
            }
        }
    }
}

// ---------------- launcher --------------------------------------------------
extern "C" void kernel_launch(void* const* d_in, const int* in_sizes, int n_in,
                              void* d_out, int out_size) {
    static bool attr_done = false;
    if (!attr_done) {
        cudaFuncSetAttribute(gemm1_kernel<true>,
                             cudaFuncAttributeMaxDynamicSharedMemorySize, G1_SMEM);
        cudaFuncSetAttribute(gemm1_kernel<false>,
                             cudaFuncAttributeMaxDynamicSharedMemorySize, G1_SMEM);
        cudaFuncSetAttribute(gemm2_kernel<true>,
                             cudaFuncAttributeMaxDynamicSharedMemorySize, G2_SMEM);
        cudaFuncSetAttribute(gemm2_kernel<false>,
                             cudaFuncAttributeMaxDynamicSharedMemorySize, G2_SMEM);
        attr_done = true;
    }

    detect_kernel<<<1, 32>>>(
        (const float*)d_in[0], (const float*)d_in[1], (const float*)d_in[2],
        (const float*)d_in[3], (const float*)d_in[4], (const float*)d_in[5],
        (const float*)d_in[6], (const float*)d_in[7], (const float*)d_in[8],
        (long long)in_sizes[0], (long long)in_sizes[1], (long long)in_sizes[2],
        (long long)in_sizes[3], (long long)in_sizes[4], (long long)in_sizes[5],
        (long long)in_sizes[6], (long long)in_sizes[7], (long long)in_sizes[8]);

    cvt_kernel<<<(WT_TOTAL / 4 + 255) / 256, 256>>>();
    router_kernel<<<T_TOK / 4, dim3(32, 4)>>>();
    gather_kernel<<<1, 1024>>>();

    // routed experts on gathered rows
    gemm1_kernel<true><<<dim3(HID / 64, T_TOK / 128, NE), 256, G1_SMEM>>>();
    gemm2_kernel<true><<<dim3(DIM / 64, T_TOK / 128, NE), 256, G2_SMEM>>>(nullptr);

    // shared experts (dense; epilogue fuses routed combine and writes out)
    gemm1_kernel<false><<<dim3(HID / 64, T_TOK / 128, NSH), 256, G1_SMEM>>>();
    gemm2_kernel<false><<<dim3(DIM / 64, T_TOK / 128, 1), 256, G2_SMEM>>>((float*)d_out);
}

// round 9
// speedup vs baseline: 2.5639x; 1.1201x over previous
#include <cuda_runtime.h>
#include <math.h>
#include <stdint.h>

#define T_TOK 4096
#define DIM   1024
#define HID   512
#define NE    8
#define NSH   2
#define NSLOT (2 * T_TOK)

// offsets (floats) inside g_wt pre-converted scratch
#define OFF_X   0
#define OFF_W1  4194304
#define OFF_W3  8388608
#define OFF_W2  12582912
#define OFF_SW1 16777216
#define OFF_SW3 17825792
#define OFF_SW2 18874368
#define WT_TOTAL 19922944   // floats (76 MB)

// ---------------- scratch (device globals; no runtime allocation) ----------
// pointer role table: 0=x 1=router_w 2=router_b 3=w1 4=w3 5=w2 6=sw1 7=sw3 8=sw2
__device__ const float* g_ptr[9];

__device__ __align__(16) float g_wt[WT_TOTAL];                  // 76 MB tf32-rounded
__device__ __align__(16) float g_gates[T_TOK * 2];
__device__ __align__(16) int   g_eidx[T_TOK * 2];
__device__ __align__(16) int   g_pos[T_TOK * 2];
__device__ __align__(16) int   g_counts[NE];
__device__ __align__(16) int   g_base[NE];
__device__ __align__(16) int   g_tok[NSLOT];
__device__ __align__(16) float g_slotgate[NSLOT];
__device__ __align__(16) float g_h[(size_t)NSLOT * HID];        // 16 MB (tf32-rounded)
__device__ __align__(16) float g_y[(size_t)NSLOT * DIM];        // 32 MB
__device__ __align__(16) float g_hsh[(size_t)NSH * T_TOK * HID];// 16 MB (tf32-rounded)

// ---------------- tf32 / cp.async helpers ----------------------------------
__device__ __forceinline__ uint32_t f2tf32(float f) {
    uint32_t u;
    asm("cvt.rna.tf32.f32 %0, %1;" : "=r"(u) : "f"(f));
    return u;
}
__device__ __forceinline__ float f2tf32f(float f) {
    return __uint_as_float(f2tf32(f));
}

__device__ __forceinline__ void mma_tf32(float c[4],
                                         uint32_t a0, uint32_t a1, uint32_t a2, uint32_t a3,
                                         uint32_t b0, uint32_t b1) {
    asm volatile(
        "mma.sync.aligned.m16n8k8.row.col.f32.tf32.tf32.f32 "
        "{%0,%1,%2,%3},{%4,%5,%6,%7},{%8,%9},{%0,%1,%2,%3};"
        : "+f"(c[0]), "+f"(c[1]), "+f"(c[2]), "+f"(c[3])
        : "r"(a0), "r"(a1), "r"(a2), "r"(a3), "r"(b0), "r"(b1));
}

__device__ __forceinline__ void cpa16(uint32_t smem_dst, const void* gsrc, int src_bytes) {
    asm volatile("cp.async.cg.shared.global [%0], [%1], 16, %2;"
                 :: "r"(smem_dst), "l"(gsrc), "r"(src_bytes));
}
__device__ __forceinline__ void cpa_commit() {
    asm volatile("cp.async.commit_group;");
}
template <int N>
__device__ __forceinline__ void cpa_wait() {
    asm volatile("cp.async.wait_group %0;" :: "n"(N));
}

// ---------------- input-role detection (content + size based) --------------
__global__ void detect_kernel(const float* p0, const float* p1, const float* p2,
                              const float* p3, const float* p4, const float* p5,
                              const float* p6, const float* p7, const float* p8,
                              long long s0, long long s1, long long s2,
                              long long s3, long long s4, long long s5,
                              long long s6, long long s7, long long s8) {
    if (threadIdx.x != 0 || blockIdx.x != 0) return;
    const float* p[9] = {p0, p1, p2, p3, p4, p5, p6, p7, p8};
    long long sz[9] = {s0, s1, s2, s3, s4, s5, s6, s7, s8};

    long long mn = sz[0];
    for (int i = 1; i < 9; i++) if (sz[i] < mn) mn = sz[i];
    long long unit = (mn == 32) ? 4 : 1;
    for (int i = 0; i < 9; i++) sz[i] /= unit;

    int pos_rb = -1, pos_rw = -1;
    int big[4]; int nb = 0;
    int med[3]; int nm = 0;
    for (int i = 0; i < 9; i++) {
        if (sz[i] == 8) pos_rb = i;
        else if (sz[i] == 8192) pos_rw = i;
        else if (sz[i] == 4194304) { if (nb < 4) big[nb] = i; nb++; }
        else if (sz[i] == 1048576) { if (nm < 3) med[nm] = i; nm++; }
    }

    bool ok = (pos_rb >= 0 && pos_rw >= 0 && nb == 4 && nm == 3);
    int pos_x = -1;
    if (ok) {
        for (int j = 0; j < 4 && pos_x < 0; j++) {
            float s = 0.f;
            const float* q = p[big[j]];
            for (int k = 0; k < 1024; k++) s += fabsf(q[k]);
            if (s * (1.f / 1024.f) > 0.1f) pos_x = big[j];
        }
        if (pos_x < 0) ok = false;
    }

    if (!ok) {
        g_ptr[0] = p[0]; g_ptr[1] = p[1]; g_ptr[2] = p[2];
        g_ptr[3] = p[3]; g_ptr[4] = p[4]; g_ptr[5] = p[5];
        g_ptr[6] = p[6]; g_ptr[7] = p[7]; g_ptr[8] = p[8];
        return;
    }

    int tr[3]; int nt = 0;
    for (int j = 0; j < 4; j++) if (big[j] != pos_x) tr[nt++] = big[j];

    g_ptr[0] = p[pos_x];
    g_ptr[1] = p[pos_rw];
    g_ptr[2] = p[pos_rb];
    if (pos_x == 0) {
        // dict-style: trios appear as (w1, w3, w2)
        g_ptr[3] = p[tr[0]]; g_ptr[4] = p[tr[1]]; g_ptr[5] = p[tr[2]];
        g_ptr[6] = p[med[0]]; g_ptr[7] = p[med[1]]; g_ptr[8] = p[med[2]];
    } else {
        // alpha-style: trios appear as (w1, w2, w3)
        g_ptr[3] = p[tr[0]]; g_ptr[4] = p[tr[2]]; g_ptr[5] = p[tr[1]];
        g_ptr[6] = p[med[0]]; g_ptr[7] = p[med[2]]; g_ptr[8] = p[med[1]];
    }
}

// ---------------- pre-convert x + all GEMM weights to tf32-rounded fp32 ----
__global__ void cvt_kernel() {
    long long i = (long long)blockIdx.x * blockDim.x + threadIdx.x;  // float4 idx
    if (i >= WT_TOTAL / 4) return;
    int role; long long b4;
    if      (i < 1048576) { role = 0; b4 = 0; }
    else if (i < 2097152) { role = 3; b4 = 1048576; }
    else if (i < 3145728) { role = 4; b4 = 2097152; }
    else if (i < 4194304) { role = 5; b4 = 3145728; }
    else if (i < 4456448) { role = 6; b4 = 4194304; }
    else if (i < 4718592) { role = 7; b4 = 4456448; }
    else                  { role = 8; b4 = 4718592; }
    float4 v = ((const float4*)g_ptr[role])[i - b4];
    float4 o;
    o.x = f2tf32f(v.x); o.y = f2tf32f(v.y);
    o.z = f2tf32f(v.z); o.w = f2tf32f(v.w);
    ((float4*)g_wt)[i] = o;
}

// ---------------- router: logits, top-2, softmax gates (pure fp32) ---------
__global__ void router_kernel() {
    const float* x  = g_ptr[0];
    const float* rw = g_ptr[1];
    const float* rb = g_ptr[2];
    int t = blockIdx.x * blockDim.y + threadIdx.y;
    if (t >= T_TOK) return;
    int lane = threadIdx.x;
    const float* xr = x + (size_t)t * DIM;

    float acc[NE];
#pragma unroll
    for (int e = 0; e < NE; e++) acc[e] = 0.f;
    for (int i = lane; i < DIM; i += 32) {
        float xv = xr[i];
        const float* w = rw + (size_t)i * NE;
#pragma unroll
        for (int e = 0; e < NE; e++) acc[e] += xv * w[e];
    }
#pragma unroll
    for (int e = 0; e < NE; e++) {
#pragma unroll
        for (int off = 16; off > 0; off >>= 1)
            acc[e] += __shfl_xor_sync(0xffffffffu, acc[e], off);
    }
    if (lane == 0) {
        float v[NE];
#pragma unroll
        for (int e = 0; e < NE; e++) v[e] = acc[e] + rb[e];
        int i0 = 0;
        for (int e = 1; e < NE; e++) if (v[e] > v[i0]) i0 = e;
        int i1 = (i0 == 0) ? 1 : 0;
        for (int e = 0; e < NE; e++) if (e != i0 && v[e] > v[i1]) i1 = e;
        float e1 = expf(v[i1] - v[i0]);
        float g0 = 1.f / (1.f + e1);
        float g1 = e1 * g0;
        g_gates[t * 2 + 0] = g0;
        g_gates[t * 2 + 1] = g1;
        g_eidx[t * 2 + 0] = i0;
        g_eidx[t * 2 + 1] = i1;
    }
}

// ---------------- parallel smem gather: 32 warps = 8 experts x 4 segments --
__global__ void __launch_bounds__(1024) gather_kernel() {
    __shared__ int   se[T_TOK * 2];     // 32 KB
    __shared__ float sg[T_TOK * 2];     // 32 KB
    __shared__ int   s_cnt[32];         // [e*4 + seg]
    __shared__ int   s_base[32];
    int tid = threadIdx.x;
    int wid = tid >> 5;
    int lane = tid & 31;

    for (int i = tid; i < T_TOK * 2; i += 1024) {
        se[i] = g_eidx[i];
        sg[i] = g_gates[i];
    }
    __syncthreads();

    int e = wid >> 2;           // expert
    int seg = wid & 3;          // token segment
    int t0 = seg * (T_TOK / 4);

    int cnt = 0;
    for (int c = 0; c < T_TOK / 4; c += 32) {
        int t = t0 + c + lane;
        bool hit = (se[t * 2] == e) || (se[t * 2 + 1] == e);
        cnt += __popc(__ballot_sync(0xffffffffu, hit));
    }
    if (lane == 0) s_cnt[wid] = cnt;
    __syncthreads();
    if (tid == 0) {
        int acc = 0;
        for (int i = 0; i < 32; i++) { s_base[i] = acc; acc += s_cnt[i]; }
    }
    __syncthreads();

    int base = s_base[wid];
    int run = 0;
    for (int c = 0; c < T_TOK / 4; c += 32) {
        int t = t0 + c + lane;
        int k = -1;
        if (se[t * 2] == e) k = 0;
        else if (se[t * 2 + 1] == e) k = 1;
        unsigned mask = __ballot_sync(0xffffffffu, k >= 0);
        if (k >= 0) {
            int slot = base + run + __popc(mask & ((1u << lane) - 1u));
            g_tok[slot] = t;
            g_pos[t * 2 + k] = slot;
            g_slotgate[slot] = sg[t * 2 + k];
        }
        run += __popc(mask);
    }
    if (lane == 0 && seg == 0) g_base[e] = s_base[wid];
    if (lane == 0 && seg == 3)
        g_counts[e] = s_base[e * 4 + 3] + s_cnt[e * 4 + 3] - s_base[e * 4];
}

// ---------------- GEMM1 (tf32 + cp.async double-buffer) --------------------
// block 128x64, BK=32, 8 warps (4x2), warp tile 32x32
// As [2][128][36] (m-major), Bs [2][32][72] (k-major)
#define G1_AS (128 * 36)
#define G1_BS (32 * 72)
#define G1_SMEM ((2 * G1_AS + 4 * G1_BS) * 4)

template <bool ROUTED>
__global__ void __launch_bounds__(256) gemm1_kernel() {
    extern __shared__ uint32_t sm[];
    int e = blockIdx.z;
    int cnt  = ROUTED ? g_counts[e] : T_TOK;
    int base = ROUTED ? g_base[e] : 0;
    int row0 = blockIdx.y * 128;
    if (row0 >= cnt) return;
    int h0 = blockIdx.x * 64;

    const float* xt = g_wt + OFF_X;
    const float* w1 = g_wt + (ROUTED ? OFF_W1 : OFF_SW1) + (size_t)e * DIM * HID;
    const float* w3 = g_wt + (ROUTED ? OFF_W3 : OFF_SW3) + (size_t)e * DIM * HID;
    float* hout = ROUTED ? (g_h + (size_t)base * HID)
                         : (g_hsh + (size_t)e * T_TOK * HID);
    const int* toklist = ROUTED ? (g_tok + base) : nullptr;

    uint32_t* As = sm;                       // 2 stages
    uint32_t* B1 = sm + 2 * G1_AS;
    uint32_t* B3 = B1 + 2 * G1_BS;
    uint32_t s_base_u = (uint32_t)__cvta_generic_to_shared(sm);

    int tid = threadIdx.x;
    int lrow = tid >> 1;
    int lkc  = (tid & 1) * 16;
    int r_l = row0 + lrow;
    const float* xrow = nullptr;
    if (r_l < cnt) { int tk = ROUTED ? toklist[r_l] : r_l; xrow = xt + (size_t)tk * DIM; }
    int lbk = tid >> 3;
    int lbn = (tid & 7) * 8;

    int wid = tid >> 5, lane = tid & 31;
    int wm = (wid >> 1) * 32;
    int wn = (wid & 1) * 32;
    int g = lane >> 2, tg = lane & 3;

    float acc1[2][4][4], acc3[2][4][4];
#pragma unroll
    for (int i = 0; i < 2; i++)
#pragma unroll
        for (int j = 0; j < 4; j++)
#pragma unroll
            for (int c = 0; c < 4; c++) { acc1[i][j][c] = 0.f; acc3[i][j][c] = 0.f; }

    auto issue = [&](int buf, int k0) {
        uint32_t a_dst = s_base_u + (uint32_t)(buf * G1_AS + lrow * 36 + lkc) * 4;
        const float* a_src = xrow ? (xrow + k0 + lkc) : xt;
        int ab = xrow ? 16 : 0;
#pragma unroll
        for (int c = 0; c < 4; c++)
            cpa16(a_dst + 16 * c, a_src + 4 * c, ab);
        uint32_t b1_dst = s_base_u + (uint32_t)(2 * G1_AS + buf * G1_BS + lbk * 72 + lbn) * 4;
        uint32_t b3_dst = s_base_u + (uint32_t)(2 * G1_AS + 2 * G1_BS + buf * G1_BS + lbk * 72 + lbn) * 4;
        const float* b1_src = w1 + (size_t)(k0 + lbk) * HID + h0 + lbn;
        const float* b3_src = w3 + (size_t)(k0 + lbk) * HID + h0 + lbn;
        cpa16(b1_dst,      b1_src,     16);
        cpa16(b1_dst + 16, b1_src + 4, 16);
        cpa16(b3_dst,      b3_src,     16);
        cpa16(b3_dst + 16, b3_src + 4, 16);
        cpa_commit();
    };

    issue(0, 0);
    int buf = 0;
    for (int k0 = 0; k0 < DIM; k0 += 32) {
        bool has_next = (k0 + 32 < DIM);
        if (has_next) { issue(buf ^ 1, k0 + 32); cpa_wait<1>(); }
        else          { cpa_wait<0>(); }
        __syncthreads();
        const uint32_t* Ab  = As + buf * G1_AS;
        const uint32_t* B1b = B1 + buf * G1_BS;
        const uint32_t* B3b = B3 + buf * G1_BS;
#pragma unroll
        for (int kk = 0; kk < 32; kk += 8) {
            uint32_t a[2][4];
#pragma unroll
            for (int i = 0; i < 2; i++) {
                int m = wm + i * 16 + g;
                a[i][0] = Ab[m * 36 + kk + tg];
                a[i][1] = Ab[(m + 8) * 36 + kk + tg];
                a[i][2] = Ab[m * 36 + kk + tg + 4];
                a[i][3] = Ab[(m + 8) * 36 + kk + tg + 4];
            }
#pragma unroll
            for (int j = 0; j < 4; j++) {
                int n = wn + j * 8 + g;
                uint32_t p0 = B1b[(kk + tg) * 72 + n];
                uint32_t p1 = B1b[(kk + tg + 4) * 72 + n];
                uint32_t q0 = B3b[(kk + tg) * 72 + n];
                uint32_t q1 = B3b[(kk + tg + 4) * 72 + n];
#pragma unroll
                for (int i = 0; i < 2; i++) {
                    mma_tf32(acc1[i][j], a[i][0], a[i][1], a[i][2], a[i][3], p0, p1);
                    mma_tf32(acc3[i][j], a[i][0], a[i][1], a[i][2], a[i][3], q0, q1);
                }
            }
        }
        __syncthreads();
        buf ^= 1;
    }

#pragma unroll
    for (int i = 0; i < 2; i++) {
        int r0 = row0 + wm + i * 16 + g;
        int r1 = r0 + 8;
#pragma unroll
        for (int j = 0; j < 4; j++) {
            int c = h0 + wn + j * 8 + 2 * tg;
            if (r0 < cnt) {
                float v0 = acc1[i][j][0], v1 = acc1[i][j][1];
                float2 o;
                o.x = f2tf32f((v0 / (1.f + expf(-v0))) * acc3[i][j][0]);
                o.y = f2tf32f((v1 / (1.f + expf(-v1))) * acc3[i][j][1]);
                *(float2*)(hout + (size_t)r0 * HID + c) = o;
            }
            if (r1 < cnt) {
                float v2 = acc1[i][j][2], v3 = acc1[i][j][3];
                float2 o;
                o.x = f2tf32f((v2 / (1.f + expf(-v2))) * acc3[i][j][2]);
                o.y = f2tf32f((v3 / (1.f + expf(-v3))) * acc3[i][j][3]);
                *(float2*)(hout + (size_t)r1 * HID + c) = o;
            }
        }
    }
}

// ---------------- GEMM2 (tf32 + cp.async double-buffer) --------------------
// ROUTED: y[slot] = (h @ w2) * gate  -> g_y
// !ROUTED: out[t] = sum_s(hsh_s @ sw2_s) + g_y[slot0(t)] + g_y[slot1(t)]  (fused combine)
#define G2_AS (128 * 36)
#define G2_BS (32 * 72)
#define G2_SMEM ((2 * G2_AS + 2 * G2_BS) * 4)

template <bool ROUTED>
__global__ void __launch_bounds__(256) gemm2_kernel(float* __restrict__ out) {
    extern __shared__ uint32_t sm[];
    int e = blockIdx.z;
    int cnt  = ROUTED ? g_counts[e] : T_TOK;
    int base = ROUTED ? g_base[e] : 0;
    int row0 = blockIdx.y * 128;
    if (row0 >= cnt) return;
    int d0 = blockIdx.x * 64;

    uint32_t* As = sm;
    uint32_t* Bs = sm + 2 * G2_AS;
    uint32_t s_base_u = (uint32_t)__cvta_generic_to_shared(sm);

    int tid = threadIdx.x;
    int lrow = tid >> 1;
    int lkc  = (tid & 1) * 16;
    int r_l = row0 + lrow;
    int lbk = tid >> 3;
    int lbn = (tid & 7) * 8;

    int wid = tid >> 5, lane = tid & 31;
    int wm = (wid >> 1) * 32;
    int wn = (wid & 1) * 32;
    int g = lane >> 2, tg = lane & 3;

    float acc[2][4][4];
#pragma unroll
    for (int i = 0; i < 2; i++)
#pragma unroll
        for (int j = 0; j < 4; j++)
#pragma unroll
            for (int c = 0; c < 4; c++) acc[i][j][c] = 0.f;

    int total_k = (ROUTED ? 1 : NSH) * HID;

    auto issue = [&](int buf, int k0) {
        int s = k0 >> 9;            // segment (shared expert index)
        int kl = k0 & (HID - 1);
        const float* A = ROUTED ? (g_h + (size_t)base * HID)
                                : (g_hsh + (size_t)s * T_TOK * HID);
        const float* w2 = g_wt + (ROUTED ? OFF_W2 : OFF_SW2)
                        + (size_t)(ROUTED ? e : s) * HID * DIM;
        uint32_t a_dst = s_base_u + (uint32_t)(buf * G2_AS + lrow * 36 + lkc) * 4;
        const float* a_src = (r_l < cnt) ? (A + (size_t)r_l * HID + kl + lkc) : A;
        int ab = (r_l < cnt) ? 16 : 0;
#pragma unroll
        for (int c = 0; c < 4; c++)
            cpa16(a_dst + 16 * c, a_src + 4 * c, ab);
        uint32_t b_dst = s_base_u + (uint32_t)(2 * G2_AS + buf * G2_BS + lbk * 72 + lbn) * 4;
        const float* b_src = w2 + (size_t)(kl + lbk) * DIM + d0 + lbn;
        cpa16(b_dst,      b_src,     16);
        cpa16(b_dst + 16, b_src + 4, 16);
        cpa_commit();
    };

    issue(0, 0);
    int buf = 0;
    for (int k0 = 0; k0 < total_k; k0 += 32) {
        bool has_next = (k0 + 32 < total_k);
        if (has_next) { issue(buf ^ 1, k0 + 32); cpa_wait<1>(); }
        else          { cpa_wait<0>(); }
        __syncthreads();
        const uint32_t* Ab = As + buf * G2_AS;
        const uint32_t* Bb = Bs + buf * G2_BS;
#pragma unroll
        for (int kk = 0; kk < 32; kk += 8) {
            uint32_t a[2][4];
#pragma unroll
            for (int i = 0; i < 2; i++) {
                int m = wm + i * 16 + g;
                a[i][0] = Ab[m * 36 + kk + tg];
                a[i][1] = Ab[(m + 8) * 36 + kk + tg];
                a[i][2] = Ab[m * 36 + kk + tg + 4];
                a[i][3] = Ab[(m + 8) * 36 + kk + tg + 4];
            }
#pragma unroll
            for (int j = 0; j < 4; j++) {
                int n = wn + j * 8 + g;
                uint32_t p0 = Bb[(kk + tg) * 72 + n];
                uint32_t p1 = Bb[(kk + tg + 4) * 72 + n];
#pragma unroll
                for (int i = 0; i < 2; i++)
                    mma_tf32(acc[i][j], a[i][0], a[i][1], a[i][2], a[i][3], p0, p1);
            }
        }
        __syncthreads();
        buf ^= 1;
    }

#pragma unroll
    for (int i = 0; i < 2; i++) {
        int r0 = row0 + wm + i * 16 + g;
        int r1 = r0 + 8;
        if (ROUTED) {
            float sc0 = (r0 < cnt) ? g_slotgate[base + r0] : 1.f;
            float sc1 = (r1 < cnt) ? g_slotgate[base + r1] : 1.f;
#pragma unroll
            for (int j = 0; j < 4; j++) {
                int c = d0 + wn + j * 8 + 2 * tg;
                if (r0 < cnt) {
                    float2 o;
                    o.x = acc[i][j][0] * sc0;
                    o.y = acc[i][j][1] * sc0;
                    *(float2*)(g_y + (size_t)(base + r0) * DIM + c) = o;
                }
                if (r1 < cnt) {
                    float2 o;
                    o.x = acc[i][j][2] * sc1;
                    o.y = acc[i][j][3] * sc1;
                    *(float2*)(g_y + (size_t)(base + r1) * DIM + c) = o;
                }
            }
        } else {
            // fused combine: out = shared_sum + routed slot contributions
            int p00 = g_pos[r0 * 2 + 0], p01 = g_pos[r0 * 2 + 1];
            int p10 = g_pos[r1 * 2 + 0], p11 = g_pos[r1 * 2 + 1];
#pragma unroll
            for (int j = 0; j < 4; j++) {
                int c = d0 + wn + j * 8 + 2 * tg;
                float2 a0 = *(const float2*)(g_y + (size_t)p00 * DIM + c);
                float2 a1 = *(const float2*)(g_y + (size_t)p01 * DIM + c);
                float2 b0 = *(const float2*)(g_y + (size_t)p10 * DIM + c);
                float2 b1 = *(const float2*)(g_y + (size_t)p11 * DIM + c);
                float2 o0, o1;
                o0.x = acc[i][j][0] + a0.x + a1.x;
                o0.y = acc[i][j][1] + a0.y + a1.y;
                o1.x = acc[i][j][2] + b0.x + b1.x;
                o1.y = acc[i][j][3] + b0.y + b1.y;
                *(float2*)(out + (size_t)r0 * DIM + c) = o0;
                *(float2*)(out + (size_t)r1 * DIM + c) = o1;
            }
        }
    }
}

// ---------------- launcher (fork-join two-stream schedule) -----------------
extern "C" void kernel_launch(void* const* d_in, const int* in_sizes, int n_in,
                              void* d_out, int out_size) {
    static cudaStream_t s1 = nullptr;
    static cudaEvent_t evDet = nullptr, evCvt = nullptr, evGat = nullptr, evSh = nullptr;
    if (s1 == nullptr) {
        cudaFuncSetAttribute(gemm1_kernel<true>,
                             cudaFuncAttributeMaxDynamicSharedMemorySize, G1_SMEM);
        cudaFuncSetAttribute(gemm1_kernel<false>,
                             cudaFuncAttributeMaxDynamicSharedMemorySize, G1_SMEM);
        cudaFuncSetAttribute(gemm2_kernel<true>,
                             cudaFuncAttributeMaxDynamicSharedMemorySize, G2_SMEM);
        cudaFuncSetAttribute(gemm2_kernel<false>,
                             cudaFuncAttributeMaxDynamicSharedMemorySize, G2_SMEM);
        cudaStreamCreateWithFlags(&s1, cudaStreamNonBlocking);
        cudaEventCreateWithFlags(&evDet, cudaEventDisableTiming);
        cudaEventCreateWithFlags(&evCvt, cudaEventDisableTiming);
        cudaEventCreateWithFlags(&evGat, cudaEventDisableTiming);
        cudaEventCreateWithFlags(&evSh,  cudaEventDisableTiming);
    }

    // s0 (capture stream): role detection
    detect_kernel<<<1, 32>>>(
        (const float*)d_in[0], (const float*)d_in[1], (const float*)d_in[2],
        (const float*)d_in[3], (const float*)d_in[4], (const float*)d_in[5],
        (const float*)d_in[6], (const float*)d_in[7], (const float*)d_in[8],
        (long long)in_sizes[0], (long long)in_sizes[1], (long long)in_sizes[2],
        (long long)in_sizes[3], (long long)in_sizes[4], (long long)in_sizes[5],
        (long long)in_sizes[6], (long long)in_sizes[7], (long long)in_sizes[8]);
    cudaEventRecord(evDet, 0);

    // s1: router + gather (reads original x; only needs detect)
    cudaStreamWaitEvent(s1, evDet, 0);
    router_kernel<<<T_TOK / 4, dim3(32, 4), 0, s1>>>();
    gather_kernel<<<1, 1024, 0, s1>>>();
    cudaEventRecord(evGat, s1);

    // s0: tf32 pre-conversion (overlaps router+gather)
    cvt_kernel<<<(WT_TOTAL / 4 + 255) / 256, 256>>>();
    cudaEventRecord(evCvt, 0);

    // s1: shared-expert gemm1 (needs cvt only) — overlaps routed path
    cudaStreamWaitEvent(s1, evCvt, 0);
    gemm1_kernel<false><<<dim3(HID / 64, T_TOK / 128, NSH), 256, G1_SMEM, s1>>>();
    cudaEventRecord(evSh, s1);

    // s0: routed path (needs gather + cvt)
    cudaStreamWaitEvent(0, evGat, 0);
    gemm1_kernel<true><<<dim3(HID / 64, T_TOK / 128, NE), 256, G1_SMEM>>>();
    gemm2_kernel<true><<<dim3(DIM / 64, T_TOK / 128, NE), 256, G2_SMEM>>>(nullptr);

    // s0: fused shared gemm2 + combine (needs routed g_y and shared g_hsh)
    cudaStreamWaitEvent(0, evSh, 0);
    gemm2_kernel<false><<<dim3(DIM / 64, T_TOK / 128, 1), 256, G2_SMEM>>>((float*)d_out);
}

// round 11
// speedup vs baseline: 3.9026x; 1.5221x over previous
#include <cuda_runtime.h>
#include <cuda_fp16.h>
#include <math.h>
#include <stdint.h>

#define T_TOK 4096
#define DIM   1024
#define HID   512
#define NE    8
#define NSH   2
#define NSLOT (2 * T_TOK)

// offsets (halves) inside g_wt scratch; weights stored TRANSPOSED [n][k] fp16
#define OFF_X   0
#define OFF_W1  4194304
#define OFF_W3  8388608
#define OFF_W2  12582912
#define OFF_SW1 16777216
#define OFF_SW3 17825792
#define OFF_SW2 18874368
#define WT_TOTAL 19922944   // halves (38 MB)

// ---------------- scratch (device globals; no runtime allocation) ----------
// pointer role table: 0=x 1=router_w 2=router_b 3=w1 4=w3 5=w2 6=sw1 7=sw3 8=sw2
__device__ const float* g_ptr[9];

__device__ __align__(16) __half g_wt[WT_TOTAL];
__device__ __align__(16) float  g_gates[T_TOK * 2];
__device__ __align__(16) int    g_eidx[T_TOK * 2];
__device__ __align__(16) int    g_pos[T_TOK * 2];
__device__ __align__(16) int    g_counts[NE];
__device__ __align__(16) int    g_base[NE];
__device__ __align__(16) int    g_tok[NSLOT];
__device__ __align__(16) float  g_slotgate[NSLOT];
__device__ __align__(16) __half g_h[(size_t)NSLOT * HID];        // 8 MB fp16
__device__ __align__(16) float  g_y[(size_t)NSLOT * DIM];        // 32 MB
__device__ __align__(16) __half g_hsh[(size_t)NSH * T_TOK * HID];// 8 MB fp16

// ---------------- helpers ---------------------------------------------------
__device__ __forceinline__ void mma_f16(float c[4],
                                        uint32_t a0, uint32_t a1, uint32_t a2, uint32_t a3,
                                        uint32_t b0, uint32_t b1) {
    asm volatile(
        "mma.sync.aligned.m16n8k16.row.col.f32.f16.f16.f32 "
        "{%0,%1,%2,%3},{%4,%5,%6,%7},{%8,%9},{%0,%1,%2,%3};"
        : "+f"(c[0]), "+f"(c[1]), "+f"(c[2]), "+f"(c[3])
        : "r"(a0), "r"(a1), "r"(a2), "r"(a3), "r"(b0), "r"(b1));
}

__device__ __forceinline__ void cpa16(uint32_t smem_dst, const void* gsrc, int src_bytes) {
    asm volatile("cp.async.cg.shared.global [%0], [%1], 16, %2;"
                 :: "r"(smem_dst), "l"(gsrc), "r"(src_bytes));
}
__device__ __forceinline__ void cpa_commit() {
    asm volatile("cp.async.commit_group;");
}
template <int N>
__device__ __forceinline__ void cpa_wait() {
    asm volatile("cp.async.wait_group %0;" :: "n"(N));
}

// ---------------- input-role detection (content + size based) --------------
__global__ void detect_kernel(const float* p0, const float* p1, const float* p2,
                              const float* p3, const float* p4, const float* p5,
                              const float* p6, const float* p7, const float* p8,
                              long long s0, long long s1, long long s2,
                              long long s3, long long s4, long long s5,
                              long long s6, long long s7, long long s8) {
    if (threadIdx.x != 0 || blockIdx.x != 0) return;
    const float* p[9] = {p0, p1, p2, p3, p4, p5, p6, p7, p8};
    long long sz[9] = {s0, s1, s2, s3, s4, s5, s6, s7, s8};

    long long mn = sz[0];
    for (int i = 1; i < 9; i++) if (sz[i] < mn) mn = sz[i];
    long long unit = (mn == 32) ? 4 : 1;
    for (int i = 0; i < 9; i++) sz[i] /= unit;

    int pos_rb = -1, pos_rw = -1;
    int big[4]; int nb = 0;
    int med[3]; int nm = 0;
    for (int i = 0; i < 9; i++) {
        if (sz[i] == 8) pos_rb = i;
        else if (sz[i] == 8192) pos_rw = i;
        else if (sz[i] == 4194304) { if (nb < 4) big[nb] = i; nb++; }
        else if (sz[i] == 1048576) { if (nm < 3) med[nm] = i; nm++; }
    }

    bool ok = (pos_rb >= 0 && pos_rw >= 0 && nb == 4 && nm == 3);
    int pos_x = -1;
    if (ok) {
        for (int j = 0; j < 4 && pos_x < 0; j++) {
            float s = 0.f;
            const float* q = p[big[j]];
            for (int k = 0; k < 1024; k++) s += fabsf(q[k]);
            if (s * (1.f / 1024.f) > 0.1f) pos_x = big[j];
        }
        if (pos_x < 0) ok = false;
    }

    if (!ok) {
        g_ptr[0] = p[0]; g_ptr[1] = p[1]; g_ptr[2] = p[2];
        g_ptr[3] = p[3]; g_ptr[4] = p[4]; g_ptr[5] = p[5];
        g_ptr[6] = p[6]; g_ptr[7] = p[7]; g_ptr[8] = p[8];
        return;
    }

    int tr[3]; int nt = 0;
    for (int j = 0; j < 4; j++) if (big[j] != pos_x) tr[nt++] = big[j];

    g_ptr[0] = p[pos_x];
    g_ptr[1] = p[pos_rw];
    g_ptr[2] = p[pos_rb];
    if (pos_x == 0) {
        // dict-style: trios appear as (w1, w3, w2)
        g_ptr[3] = p[tr[0]]; g_ptr[4] = p[tr[1]]; g_ptr[5] = p[tr[2]];
        g_ptr[6] = p[med[0]]; g_ptr[7] = p[med[1]]; g_ptr[8] = p[med[2]];
    } else {
        // alpha-style: trios appear as (w1, w2, w3)
        g_ptr[3] = p[tr[0]]; g_ptr[4] = p[tr[2]]; g_ptr[5] = p[tr[1]];
        g_ptr[6] = p[med[0]]; g_ptr[7] = p[med[2]]; g_ptr[8] = p[med[1]];
    }
}

// ---------------- x: fp32 -> fp16 copy --------------------------------------
__global__ void xcvt_kernel() {
    int i = blockIdx.x * blockDim.x + threadIdx.x;   // float4 index (1M total)
    float4 v = ((const float4*)g_ptr[0])[i];
    __half2* dst = (__half2*)(g_wt + OFF_X);
    dst[2 * i + 0] = __floats2half2_rn(v.x, v.y);
    dst[2 * i + 1] = __floats2half2_rn(v.z, v.w);
}

// ---------------- weights: tiled TRANSPOSE + fp16 convert -------------------
// out[c][r] = half(in[r][c]).  z selects (matrix, expert).
__global__ void wtr_kernel() {
    __shared__ float tile[32][33];
    int z = blockIdx.z;
    const float* src; __half* dst; int R, C;
    if (z < 8)       { src = g_ptr[3] + (size_t)z * DIM * HID;        dst = g_wt + OFF_W1 + (size_t)z * DIM * HID;        R = DIM; C = HID; }
    else if (z < 16) { int e = z - 8;  src = g_ptr[4] + (size_t)e * DIM * HID; dst = g_wt + OFF_W3 + (size_t)e * DIM * HID; R = DIM; C = HID; }
    else if (z < 24) { int e = z - 16; src = g_ptr[5] + (size_t)e * HID * DIM; dst = g_wt + OFF_W2 + (size_t)e * HID * DIM; R = HID; C = DIM; }
    else if (z < 26) { int e = z - 24; src = g_ptr[6] + (size_t)e * DIM * HID; dst = g_wt + OFF_SW1 + (size_t)e * DIM * HID; R = DIM; C = HID; }
    else if (z < 28) { int e = z - 26; src = g_ptr[7] + (size_t)e * DIM * HID; dst = g_wt + OFF_SW3 + (size_t)e * DIM * HID; R = DIM; C = HID; }
    else             { int e = z - 28; src = g_ptr[8] + (size_t)e * HID * DIM; dst = g_wt + OFF_SW2 + (size_t)e * HID * DIM; R = HID; C = DIM; }

    int r0 = blockIdx.y * 32, c0 = blockIdx.x * 32;
    if (r0 >= R || c0 >= C) return;
    int tx = threadIdx.x, ty = threadIdx.y;
#pragma unroll
    for (int j = 0; j < 4; j++)
        tile[ty + 8 * j][tx] = src[(size_t)(r0 + ty + 8 * j) * C + c0 + tx];
    __syncthreads();
#pragma unroll
    for (int j = 0; j < 4; j++)
        dst[(size_t)(c0 + ty + 8 * j) * R + r0 + tx] = __float2half_rn(tile[tx][ty + 8 * j]);
}

// ---------------- router: logits, top-2, softmax gates (pure fp32) ---------
__global__ void router_kernel() {
    const float* x  = g_ptr[0];
    const float* rw = g_ptr[1];
    const float* rb = g_ptr[2];
    int t = blockIdx.x * blockDim.y + threadIdx.y;
    if (t >= T_TOK) return;
    int lane = threadIdx.x;
    const float* xr = x + (size_t)t * DIM;

    float acc[NE];
#pragma unroll
    for (int e = 0; e < NE; e++) acc[e] = 0.f;
    for (int i = lane; i < DIM; i += 32) {
        float xv = xr[i];
        const float* w = rw + (size_t)i * NE;
#pragma unroll
        for (int e = 0; e < NE; e++) acc[e] += xv * w[e];
    }
#pragma unroll
    for (int e = 0; e < NE; e++) {
#pragma unroll
        for (int off = 16; off > 0; off >>= 1)
            acc[e] += __shfl_xor_sync(0xffffffffu, acc[e], off);
    }
    if (lane == 0) {
        float v[NE];
#pragma unroll
        for (int e = 0; e < NE; e++) v[e] = acc[e] + rb[e];
        int i0 = 0;
        for (int e = 1; e < NE; e++) if (v[e] > v[i0]) i0 = e;
        int i1 = (i0 == 0) ? 1 : 0;
        for (int e = 0; e < NE; e++) if (e != i0 && v[e] > v[i1]) i1 = e;
        float e1 = expf(v[i1] - v[i0]);
        float g0 = 1.f / (1.f + e1);
        float g1 = e1 * g0;
        g_gates[t * 2 + 0] = g0;
        g_gates[t * 2 + 1] = g1;
        g_eidx[t * 2 + 0] = i0;
        g_eidx[t * 2 + 1] = i1;
    }
}

// ---------------- parallel smem gather: 32 warps = 8 experts x 4 segments --
__global__ void __launch_bounds__(1024) gather_kernel() {
    __shared__ int   se[T_TOK * 2];
    __shared__ float sg[T_TOK * 2];
    __shared__ int   s_cnt[32];
    __shared__ int   s_base[32];
    int tid = threadIdx.x;
    int wid = tid >> 5;
    int lane = tid & 31;

    for (int i = tid; i < T_TOK * 2; i += 1024) {
        se[i] = g_eidx[i];
        sg[i] = g_gates[i];
    }
    __syncthreads();

    int e = wid >> 2;
    int seg = wid & 3;
    int t0 = seg * (T_TOK / 4);

    int cnt = 0;
    for (int c = 0; c < T_TOK / 4; c += 32) {
        int t = t0 + c + lane;
        bool hit = (se[t * 2] == e) || (se[t * 2 + 1] == e);
        cnt += __popc(__ballot_sync(0xffffffffu, hit));
    }
    if (lane == 0) s_cnt[wid] = cnt;
    __syncthreads();
    if (tid == 0) {
        int acc = 0;
        for (int i = 0; i < 32; i++) { s_base[i] = acc; acc += s_cnt[i]; }
    }
    __syncthreads();

    int base = s_base[wid];
    int run = 0;
    for (int c = 0; c < T_TOK / 4; c += 32) {
        int t = t0 + c + lane;
        int k = -1;
        if (se[t * 2] == e) k = 0;
        else if (se[t * 2 + 1] == e) k = 1;
        unsigned mask = __ballot_sync(0xffffffffu, k >= 0);
        if (k >= 0) {
            int slot = base + run + __popc(mask & ((1u << lane) - 1u));
            g_tok[slot] = t;
            g_pos[t * 2 + k] = slot;
            g_slotgate[slot] = sg[t * 2 + k];
        }
        run += __popc(mask);
    }
    if (lane == 0 && seg == 0) g_base[e] = s_base[wid];
    if (lane == 0 && seg == 3)
        g_counts[e] = s_base[e * 4 + 3] + s_cnt[e * 4 + 3] - s_base[e * 4];
}

// ---------------- GEMM geometry ---------------------------------------------
// block 128x64, BK=64 halves, 8 warps (4x2), warp tile 32x32, m16n8k16 fp16
// A smem [m][k] pad 72 halves/row; B smem [n][k] pad 72 (weights pre-transposed)
#define PADH 72
#define A_ST (128 * PADH)   // halves per A stage
#define B_ST (64 * PADH)    // halves per B stage
#define G1_SMEM ((2 * A_ST + 4 * B_ST) * 2)
#define G2_SMEM ((2 * A_ST + 2 * B_ST) * 2)

// ---------------- GEMM1 (fp16 mma): h = silu(x@w1) * (x@w3) ----------------
template <bool ROUTED>
__global__ void __launch_bounds__(256) gemm1_kernel() {
    extern __shared__ __half sm[];
    int e = blockIdx.z;
    int cnt  = ROUTED ? g_counts[e] : T_TOK;
    int base = ROUTED ? g_base[e] : 0;
    int row0 = blockIdx.y * 128;
    if (row0 >= cnt) return;
    int h0 = blockIdx.x * 64;

    const __half* xt  = g_wt + OFF_X;
    const __half* w1t = g_wt + (ROUTED ? OFF_W1 : OFF_SW1) + (size_t)e * DIM * HID; // [HID][DIM]
    const __half* w3t = g_wt + (ROUTED ? OFF_W3 : OFF_SW3) + (size_t)e * DIM * HID;
    __half* hout = ROUTED ? (g_h + (size_t)base * HID)
                          : (g_hsh + (size_t)e * T_TOK * HID);
    const int* toklist = ROUTED ? (g_tok + base) : nullptr;

    uint32_t sbu = (uint32_t)__cvta_generic_to_shared(sm);
    const uint32_t* Asw = (const uint32_t*)sm;
    const uint32_t* B1w = (const uint32_t*)(sm + 2 * A_ST);
    const uint32_t* B3w = (const uint32_t*)(sm + 2 * A_ST + 2 * B_ST);

    int tid = threadIdx.x;
    int lrow = tid >> 1;
    int lkc  = (tid & 1) * 32;
    int r_l = row0 + lrow;
    const __half* arow = nullptr;
    if (r_l < cnt) { int tk = ROUTED ? toklist[r_l] : r_l; arow = xt + (size_t)tk * DIM; }
    int lbrow = tid >> 2;
    int lbc   = (tid & 3) * 16;
    const __half* b1row = w1t + (size_t)(h0 + lbrow) * DIM;
    const __half* b3row = w3t + (size_t)(h0 + lbrow) * DIM;

    int wid = tid >> 5, lane = tid & 31;
    int wm = (wid >> 1) * 32;
    int wn = (wid & 1) * 32;
    int g = lane >> 2, tg = lane & 3;

    float acc1[2][4][4], acc3[2][4][4];
#pragma unroll
    for (int i = 0; i < 2; i++)
#pragma unroll
        for (int j = 0; j < 4; j++)
#pragma unroll
            for (int c = 0; c < 4; c++) { acc1[i][j][c] = 0.f; acc3[i][j][c] = 0.f; }

    auto issue = [&](int buf, int k0) {
        uint32_t a_dst = sbu + (uint32_t)(buf * A_ST + lrow * PADH + lkc) * 2;
        const __half* a_src = arow ? (arow + k0 + lkc) : xt;
        int ab = arow ? 16 : 0;
#pragma unroll
        for (int c = 0; c < 4; c++)
            cpa16(a_dst + 16 * c, a_src + 8 * c, ab);
        uint32_t b1_dst = sbu + (uint32_t)((2 * A_ST + buf * B_ST) + lbrow * PADH + lbc) * 2;
        uint32_t b3_dst = sbu + (uint32_t)((2 * A_ST + 2 * B_ST + buf * B_ST) + lbrow * PADH + lbc) * 2;
        const __half* b1s = b1row + k0 + lbc;
        const __half* b3s = b3row + k0 + lbc;
        cpa16(b1_dst,      b1s,     16);
        cpa16(b1_dst + 16, b1s + 8, 16);
        cpa16(b3_dst,      b3s,     16);
        cpa16(b3_dst + 16, b3s + 8, 16);
        cpa_commit();
    };

    issue(0, 0);
    int buf = 0;
    const int S = DIM / 64;
    for (int s = 0; s < S; s++) {
        if (s + 1 < S) { issue(buf ^ 1, (s + 1) * 64); cpa_wait<1>(); }
        else           { cpa_wait<0>(); }
        __syncthreads();
        const uint32_t* Ab  = Asw + buf * (A_ST / 2);
        const uint32_t* B1b = B1w + buf * (B_ST / 2);
        const uint32_t* B3b = B3w + buf * (B_ST / 2);
#pragma unroll
        for (int kk4 = 0; kk4 < 4; kk4++) {
            uint32_t a[2][4];
#pragma unroll
            for (int i = 0; i < 2; i++) {
                int m = wm + i * 16 + g;
                int bidx = m * (PADH / 2) + kk4 * 8 + tg;
                a[i][0] = Ab[bidx];
                a[i][1] = Ab[bidx + 8 * (PADH / 2)];
                a[i][2] = Ab[bidx + 4];
                a[i][3] = Ab[bidx + 8 * (PADH / 2) + 4];
            }
#pragma unroll
            for (int j = 0; j < 4; j++) {
                int n = wn + j * 8 + g;
                int nb = n * (PADH / 2) + kk4 * 8 + tg;
                uint32_t p0 = B1b[nb], p1 = B1b[nb + 4];
                uint32_t q0 = B3b[nb], q1 = B3b[nb + 4];
#pragma unroll
                for (int i = 0; i < 2; i++) {
                    mma_f16(acc1[i][j], a[i][0], a[i][1], a[i][2], a[i][3], p0, p1);
                    mma_f16(acc3[i][j], a[i][0], a[i][1], a[i][2], a[i][3], q0, q1);
                }
            }
        }
        __syncthreads();
        buf ^= 1;
    }

#pragma unroll
    for (int i = 0; i < 2; i++) {
        int r0 = row0 + wm + i * 16 + g;
        int r1 = r0 + 8;
#pragma unroll
        for (int j = 0; j < 4; j++) {
            int c = h0 + wn + j * 8 + 2 * tg;
            if (r0 < cnt) {
                float v0 = acc1[i][j][0], v1 = acc1[i][j][1];
                *(__half2*)(hout + (size_t)r0 * HID + c) = __floats2half2_rn(
                    (v0 / (1.f + expf(-v0))) * acc3[i][j][0],
                    (v1 / (1.f + expf(-v1))) * acc3[i][j][1]);
            }
            if (r1 < cnt) {
                float v2 = acc1[i][j][2], v3 = acc1[i][j][3];
                *(__half2*)(hout + (size_t)r1 * HID + c) = __floats2half2_rn(
                    (v2 / (1.f + expf(-v2))) * acc3[i][j][2],
                    (v3 / (1.f + expf(-v3))) * acc3[i][j][3]);
            }
        }
    }
}

// ---------------- GEMM2 (fp16 mma) ------------------------------------------
// ROUTED: g_y[slot] = (h @ w2) * gate ; !ROUTED: out = sum_s hsh@sw2 + combine
template <bool ROUTED>
__global__ void __launch_bounds__(256) gemm2_kernel(float* __restrict__ out) {
    extern __shared__ __half sm[];
    int e = blockIdx.z;
    int cnt  = ROUTED ? g_counts[e] : T_TOK;
    int base = ROUTED ? g_base[e] : 0;
    int row0 = blockIdx.y * 128;
    if (row0 >= cnt) return;
    int d0 = blockIdx.x * 64;

    uint32_t sbu = (uint32_t)__cvta_generic_to_shared(sm);
    const uint32_t* Asw = (const uint32_t*)sm;
    const uint32_t* Bw  = (const uint32_t*)(sm + 2 * A_ST);

    int tid = threadIdx.x;
    int lrow = tid >> 1;
    int lkc  = (tid & 1) * 32;
    int r_l = row0 + lrow;
    bool aval = (r_l < cnt);
    int lbrow = tid >> 2;
    int lbc   = (tid & 3) * 16;

    int wid = tid >> 5, lane = tid & 31;
    int wm = (wid >> 1) * 32;
    int wn = (wid & 1) * 32;
    int g = lane >> 2, tg = lane & 3;

    float acc[2][4][4];
#pragma unroll
    for (int i = 0; i < 2; i++)
#pragma unroll
        for (int j = 0; j < 4; j++)
#pragma unroll
            for (int c = 0; c < 4; c++) acc[i][j][c] = 0.f;

    int total_k = (ROUTED ? 1 : NSH) * HID;

    auto issue = [&](int buf, int k0) {
        int seg = k0 >> 9;
        int kl = k0 & (HID - 1);
        const __half* A = ROUTED ? (g_h + (size_t)base * HID)
                                 : (g_hsh + (size_t)seg * T_TOK * HID);
        const __half* w2t = g_wt + (ROUTED ? OFF_W2 : OFF_SW2)
                          + (size_t)(ROUTED ? e : seg) * HID * DIM;   // [DIM][HID]
        uint32_t a_dst = sbu + (uint32_t)(buf * A_ST + lrow * PADH + lkc) * 2;
        const __half* a_src = aval ? (A + (size_t)r_l * HID + kl + lkc) : A;
        int ab = aval ? 16 : 0;
#pragma unroll
        for (int c = 0; c < 4; c++)
            cpa16(a_dst + 16 * c, a_src + 8 * c, ab);
        uint32_t b_dst = sbu + (uint32_t)((2 * A_ST + buf * B_ST) + lbrow * PADH + lbc) * 2;
        const __half* b_src = w2t + (size_t)(d0 + lbrow) * HID + kl + lbc;
        cpa16(b_dst,      b_src,     16);
        cpa16(b_dst + 16, b_src + 8, 16);
        cpa_commit();
    };

    issue(0, 0);
    int buf = 0;
    const int S = total_k / 64;
    for (int s = 0; s < S; s++) {
        if (s + 1 < S) { issue(buf ^ 1, (s + 1) * 64); cpa_wait<1>(); }
        else           { cpa_wait<0>(); }
        __syncthreads();
        const uint32_t* Ab = Asw + buf * (A_ST / 2);
        const uint32_t* Bb = Bw + buf * (B_ST / 2);
#pragma unroll
        for (int kk4 = 0; kk4 < 4; kk4++) {
            uint32_t a[2][4];
#pragma unroll
            for (int i = 0; i < 2; i++) {
                int m = wm + i * 16 + g;
                int bidx = m * (PADH / 2) + kk4 * 8 + tg;
                a[i][0] = Ab[bidx];
                a[i][1] = Ab[bidx + 8 * (PADH / 2)];
                a[i][2] = Ab[bidx + 4];
                a[i][3] = Ab[bidx + 8 * (PADH / 2) + 4];
            }
#pragma unroll
            for (int j = 0; j < 4; j++) {
                int n = wn + j * 8 + g;
                int nb = n * (PADH / 2) + kk4 * 8 + tg;
                uint32_t p0 = Bb[nb], p1 = Bb[nb + 4];
#pragma unroll
                for (int i = 0; i < 2; i++)
                    mma_f16(acc[i][j], a[i][0], a[i][1], a[i][2], a[i][3], p0, p1);
            }
        }
        __syncthreads();
        buf ^= 1;
    }

#pragma unroll
    for (int i = 0; i < 2; i++) {
        int r0 = row0 + wm + i * 16 + g;
        int r1 = r0 + 8;
        if (ROUTED) {
            float sc0 = (r0 < cnt) ? g_slotgate[base + r0] : 1.f;
            float sc1 = (r1 < cnt) ? g_slotgate[base + r1] : 1.f;
#pragma unroll
            for (int j = 0; j < 4; j++) {
                int c = d0 + wn + j * 8 + 2 * tg;
                if (r0 < cnt) {
                    float2 o;
                    o.x = acc[i][j][0] * sc0;
                    o.y = acc[i][j][1] * sc0;
                    *(float2*)(g_y + (size_t)(base + r0) * DIM + c) = o;
                }
                if (r1 < cnt) {
                    float2 o;
                    o.x = acc[i][j][2] * sc1;
                    o.y = acc[i][j][3] * sc1;
                    *(float2*)(g_y + (size_t)(base + r1) * DIM + c) = o;
                }
            }
        } else {
            int p00 = g_pos[r0 * 2 + 0], p01 = g_pos[r0 * 2 + 1];
            int p10 = g_pos[r1 * 2 + 0], p11 = g_pos[r1 * 2 + 1];
#pragma unroll
            for (int j = 0; j < 4; j++) {
                int c = d0 + wn + j * 8 + 2 * tg;
                float2 a0 = *(const float2*)(g_y + (size_t)p00 * DIM + c);
                float2 a1 = *(const float2*)(g_y + (size_t)p01 * DIM + c);
                float2 b0 = *(const float2*)(g_y + (size_t)p10 * DIM + c);
                float2 b1 = *(const float2*)(g_y + (size_t)p11 * DIM + c);
                float2 o0, o1;
                o0.x = acc[i][j][0] + a0.x + a1.x;
                o0.y = acc[i][j][1] + a0.y + a1.y;
                o1.x = acc[i][j][2] + b0.x + b1.x;
                o1.y = acc[i][j][3] + b0.y + b1.y;
                *(float2*)(out + (size_t)r0 * DIM + c) = o0;
                *(float2*)(out + (size_t)r1 * DIM + c) = o1;
            }
        }
    }
}

// ---------------- launcher (fork-join two-stream schedule) -----------------
extern "C" void kernel_launch(void* const* d_in, const int* in_sizes, int n_in,
                              void* d_out, int out_size) {
    static cudaStream_t s1 = nullptr;
    static cudaEvent_t evDet = nullptr, evCvt = nullptr, evGat = nullptr, evSh = nullptr;
    if (s1 == nullptr) {
        cudaFuncSetAttribute(gemm1_kernel<true>,
                             cudaFuncAttributeMaxDynamicSharedMemorySize, G1_SMEM);
        cudaFuncSetAttribute(gemm1_kernel<false>,
                             cudaFuncAttributeMaxDynamicSharedMemorySize, G1_SMEM);
        cudaFuncSetAttribute(gemm2_kernel<true>,
                             cudaFuncAttributeMaxDynamicSharedMemorySize, G2_SMEM);
        cudaFuncSetAttribute(gemm2_kernel<false>,
                             cudaFuncAttributeMaxDynamicSharedMemorySize, G2_SMEM);
        cudaStreamCreateWithFlags(&s1, cudaStreamNonBlocking);
        cudaEventCreateWithFlags(&evDet, cudaEventDisableTiming);
        cudaEventCreateWithFlags(&evCvt, cudaEventDisableTiming);
        cudaEventCreateWithFlags(&evGat, cudaEventDisableTiming);
        cudaEventCreateWithFlags(&evSh,  cudaEventDisableTiming);
    }

    detect_kernel<<<1, 32>>>(
        (const float*)d_in[0], (const float*)d_in[1], (const float*)d_in[2],
        (const float*)d_in[3], (const float*)d_in[4], (const float*)d_in[5],
        (const float*)d_in[6], (const float*)d_in[7], (const float*)d_in[8],
        (long long)in_sizes[0], (long long)in_sizes[1], (long long)in_sizes[2],
        (long long)in_sizes[3], (long long)in_sizes[4], (long long)in_sizes[5],
        (long long)in_sizes[6], (long long)in_sizes[7], (long long)in_sizes[8]);
    cudaEventRecord(evDet, 0);

    // s1: router + gather (reads original fp32 x)
    cudaStreamWaitEvent(s1, evDet, 0);
    router_kernel<<<T_TOK / 4, dim3(32, 4), 0, s1>>>();
    gather_kernel<<<1, 1024, 0, s1>>>();
    cudaEventRecord(evGat, s1);

    // s0: fp16 conversion (x copy + weight transpose) — overlaps router+gather
    xcvt_kernel<<<T_TOK * DIM / 4 / 256, 256>>>();
    wtr_kernel<<<dim3(32, 32, 30), dim3(32, 8)>>>();
    cudaEventRecord(evCvt, 0);

    // s1: shared-expert gemm1 (needs cvt only) — overlaps routed path
    cudaStreamWaitEvent(s1, evCvt, 0);
    gemm1_kernel<false><<<dim3(HID / 64, T_TOK / 128, NSH), 256, G1_SMEM, s1>>>();
    cudaEventRecord(evSh, s1);

    // s0: routed path (needs gather + cvt)
    cudaStreamWaitEvent(0, evGat, 0);
    gemm1_kernel<true><<<dim3(HID / 64, T_TOK / 128, NE), 256, G1_SMEM>>>();
    gemm2_kernel<true><<<dim3(DIM / 64, T_TOK / 128, NE), 256, G2_SMEM>>>(nullptr);

    // s0: fused shared gemm2 + combine
    cudaStreamWaitEvent(0, evSh, 0);
    gemm2_kernel<false><<<dim3(DIM / 64, T_TOK / 128, 1), 256, G2_SMEM>>>((float*)d_out);
}